// round 1
// baseline (speedup 1.0000x reference)
#include <cuda_runtime.h>
#include <mma.h>
#include <cstdint>

using namespace nvcuda;

namespace {
constexpr int kNodes = 50000;
constexpr int kEdges = 500000;
constexpr int BM = 64, BN = 64, BK = 32, NTHREADS = 128;
}

// Static scratch (allocation-free rule: __device__ globals)
__device__ float g_node_f[(size_t)kNodes * 128];   //  25.6 MB
__device__ float g_edge_f[(size_t)kEdges * 128];   //   256 MB
__device__ float g_h1[(size_t)kEdges * 512];       //  1024 MB
__device__ float g_h2[(size_t)kEdges * 256];       //   512 MB
__device__ int   g_src[kEdges];
__device__ int   g_dst[kEdges];
__device__ int   g_is64;

// ---------------------------------------------------------------------------
// edge_index dtype detection: if data is int64, every 8-byte word is a valid
// node id in [0, kNodes). If it is int32, the high 32 bits of each 8-byte word
// hold another random index (nonzero w.h.p.), so the check fails.
// ---------------------------------------------------------------------------
__global__ void detect_idx_kernel(const void* idx) {
    if (threadIdx.x == 0 && blockIdx.x == 0) {
        const long long* p = (const long long*)idx;
        int ok = 1;
        for (int i = 0; i < 256; ++i) {
            long long v = p[i];
            if (v < 0 || v >= kNodes) { ok = 0; break; }
        }
        g_is64 = ok;
    }
}

__global__ void conv_idx_kernel(const void* idx) {
    int i = blockIdx.x * blockDim.x + threadIdx.x;
    if (i >= kEdges) return;
    int s, d;
    if (g_is64) {
        const long long* p = (const long long*)idx;
        s = (int)p[i];
        d = (int)p[kEdges + i];
    } else {
        const int* p = (const int*)idx;
        s = p[i];
        d = p[kEdges + i];
    }
    g_src[i] = s;
    g_dst[i] = d;
}

// ---------------------------------------------------------------------------
// Generic TF32 wmma GEMM: C[M,N] = relu?(A[M,K] @ B[K,N] + bias[N])
// Requirements: K % 32 == 0, N % 64 == 0 (all layers satisfy this); only M is
// guarded. 64x64 block tile, 4 warps each computing 32x32 (2x2 wmma frags).
// ---------------------------------------------------------------------------
template <bool RELU>
__global__ __launch_bounds__(NTHREADS)
void gemm_bias_kernel(const float* __restrict__ A, const float* __restrict__ B,
                      const float* __restrict__ bias, float* __restrict__ C,
                      int M, int N, int K)
{
    __shared__ float sA[BM][BK];
    __shared__ float sB[BK][BN];
    __shared__ float sC[BM][BN];

    const int bm = blockIdx.x * BM;
    const int bn = blockIdx.y * BN;
    const int tid = threadIdx.x;
    const int warp = tid >> 5;
    const int wm = (warp >> 1) * 32;
    const int wn = (warp & 1) * 32;

    wmma::fragment<wmma::accumulator, 16, 16, 8, float> acc[2][2];
#pragma unroll
    for (int i = 0; i < 2; ++i)
#pragma unroll
        for (int j = 0; j < 2; ++j) wmma::fill_fragment(acc[i][j], 0.0f);

    for (int k0 = 0; k0 < K; k0 += BK) {
        // A tile: 64x32 floats = 512 float4, 4 per thread
#pragma unroll
        for (int it = 0; it < 4; ++it) {
            int idx = tid + it * NTHREADS;
            int r = idx >> 3, c4 = idx & 7;
            int gm = bm + r;
            float4 v = make_float4(0.f, 0.f, 0.f, 0.f);
            if (gm < M) v = *(const float4*)(A + (size_t)gm * K + k0 + c4 * 4);
            *(float4*)(&sA[r][c4 * 4]) = v;
        }
        // B tile: 32x64 floats = 512 float4
#pragma unroll
        for (int it = 0; it < 4; ++it) {
            int idx = tid + it * NTHREADS;
            int r = idx >> 4, c4 = idx & 15;
            float4 v = *(const float4*)(B + (size_t)(k0 + r) * N + bn + c4 * 4);
            *(float4*)(&sB[r][c4 * 4]) = v;
        }
        __syncthreads();

#pragma unroll
        for (int kk = 0; kk < BK; kk += 8) {
            wmma::fragment<wmma::matrix_a, 16, 16, 8, wmma::precision::tf32, wmma::row_major> a[2];
            wmma::fragment<wmma::matrix_b, 16, 16, 8, wmma::precision::tf32, wmma::row_major> b[2];
            wmma::load_matrix_sync(a[0], &sA[wm][kk], BK);
            wmma::load_matrix_sync(a[1], &sA[wm + 16][kk], BK);
            wmma::load_matrix_sync(b[0], &sB[kk][wn], BN);
            wmma::load_matrix_sync(b[1], &sB[kk][wn + 16], BN);
#pragma unroll
            for (int f = 0; f < 2; ++f) {
#pragma unroll
                for (int t = 0; t < a[f].num_elements; ++t)
                    a[f].x[t] = wmma::__float_to_tf32(a[f].x[t]);
#pragma unroll
                for (int t = 0; t < b[f].num_elements; ++t)
                    b[f].x[t] = wmma::__float_to_tf32(b[f].x[t]);
            }
#pragma unroll
            for (int i = 0; i < 2; ++i)
#pragma unroll
                for (int j = 0; j < 2; ++j)
                    wmma::mma_sync(acc[i][j], a[i], b[j], acc[i][j]);
        }
        __syncthreads();
    }

#pragma unroll
    for (int i = 0; i < 2; ++i)
#pragma unroll
        for (int j = 0; j < 2; ++j)
            wmma::store_matrix_sync(&sC[wm + i * 16][wn + j * 16], acc[i][j], BN,
                                    wmma::mem_row_major);
    __syncthreads();

#pragma unroll
    for (int it = 0; it < 8; ++it) {
        int idx = tid + it * NTHREADS;
        int r = idx >> 4, c4 = idx & 15;
        int gm = bm + r;
        if (gm < M) {
            float4 v = *(float4*)(&sC[r][c4 * 4]);
            int gn = bn + c4 * 4;
            const float4 bb = *(const float4*)(bias + gn);
            v.x += bb.x; v.y += bb.y; v.z += bb.z; v.w += bb.w;
            if (RELU) {
                v.x = fmaxf(v.x, 0.f); v.y = fmaxf(v.y, 0.f);
                v.z = fmaxf(v.z, 0.f); v.w = fmaxf(v.w, 0.f);
            }
            *(float4*)(C + (size_t)gm * N + gn) = v;
        }
    }
}

// ---------------------------------------------------------------------------
// W1 layer with fused gather: logical A row e = concat(node_f[src[e]],
// node_f[dst[e]], edge_f[e])  (K = 384). Avoids materializing the 768 MB
// "combined" tensor. K-chunks of 32 never straddle a segment boundary.
// ---------------------------------------------------------------------------
__global__ __launch_bounds__(NTHREADS)
void gemm_gather_kernel(const float* __restrict__ W1, const float* __restrict__ b1,
                        float* __restrict__ C)
{
    constexpr int K = 384, N = 512, M = kEdges;
    __shared__ float sA[BM][BK];
    __shared__ float sB[BK][BN];
    __shared__ float sC[BM][BN];
    __shared__ int sSrc[BM], sDst[BM];

    const int bm = blockIdx.x * BM;
    const int bn = blockIdx.y * BN;
    const int tid = threadIdx.x;
    const int warp = tid >> 5;
    const int wm = (warp >> 1) * 32;
    const int wn = (warp & 1) * 32;

    if (tid < BM) {
        int e = bm + tid;
        sSrc[tid] = (e < M) ? g_src[e] : 0;
        sDst[tid] = (e < M) ? g_dst[e] : 0;
    }
    __syncthreads();

    wmma::fragment<wmma::accumulator, 16, 16, 8, float> acc[2][2];
#pragma unroll
    for (int i = 0; i < 2; ++i)
#pragma unroll
        for (int j = 0; j < 2; ++j) wmma::fill_fragment(acc[i][j], 0.0f);

    for (int k0 = 0; k0 < K; k0 += BK) {
#pragma unroll
        for (int it = 0; it < 4; ++it) {
            int idx = tid + it * NTHREADS;
            int r = idx >> 3, c4 = idx & 7;
            int e = bm + r;
            const float* base;
            if (k0 < 128)      base = g_node_f + (size_t)sSrc[r] * 128 + k0;
            else if (k0 < 256) base = g_node_f + (size_t)sDst[r] * 128 + (k0 - 128);
            else               base = g_edge_f + (size_t)e * 128 + (k0 - 256);
            float4 v = make_float4(0.f, 0.f, 0.f, 0.f);
            if (e < M) v = *(const float4*)(base + c4 * 4);
            *(float4*)(&sA[r][c4 * 4]) = v;
        }
#pragma unroll
        for (int it = 0; it < 4; ++it) {
            int idx = tid + it * NTHREADS;
            int r = idx >> 4, c4 = idx & 15;
            float4 v = *(const float4*)(W1 + (size_t)(k0 + r) * N + bn + c4 * 4);
            *(float4*)(&sB[r][c4 * 4]) = v;
        }
        __syncthreads();

#pragma unroll
        for (int kk = 0; kk < BK; kk += 8) {
            wmma::fragment<wmma::matrix_a, 16, 16, 8, wmma::precision::tf32, wmma::row_major> a[2];
            wmma::fragment<wmma::matrix_b, 16, 16, 8, wmma::precision::tf32, wmma::row_major> b[2];
            wmma::load_matrix_sync(a[0], &sA[wm][kk], BK);
            wmma::load_matrix_sync(a[1], &sA[wm + 16][kk], BK);
            wmma::load_matrix_sync(b[0], &sB[kk][wn], BN);
            wmma::load_matrix_sync(b[1], &sB[kk][wn + 16], BN);
#pragma unroll
            for (int f = 0; f < 2; ++f) {
#pragma unroll
                for (int t = 0; t < a[f].num_elements; ++t)
                    a[f].x[t] = wmma::__float_to_tf32(a[f].x[t]);
#pragma unroll
                for (int t = 0; t < b[f].num_elements; ++t)
                    b[f].x[t] = wmma::__float_to_tf32(b[f].x[t]);
            }
#pragma unroll
            for (int i = 0; i < 2; ++i)
#pragma unroll
                for (int j = 0; j < 2; ++j)
                    wmma::mma_sync(acc[i][j], a[i], b[j], acc[i][j]);
        }
        __syncthreads();
    }

#pragma unroll
    for (int i = 0; i < 2; ++i)
#pragma unroll
        for (int j = 0; j < 2; ++j)
            wmma::store_matrix_sync(&sC[wm + i * 16][wn + j * 16], acc[i][j], BN,
                                    wmma::mem_row_major);
    __syncthreads();

#pragma unroll
    for (int it = 0; it < 8; ++it) {
        int idx = tid + it * NTHREADS;
        int r = idx >> 4, c4 = idx & 15;
        int gm = bm + r;
        if (gm < M) {
            float4 v = *(float4*)(&sC[r][c4 * 4]);
            int gn = bn + c4 * 4;
            const float4 bb = *(const float4*)(b1 + gn);
            v.x = fmaxf(v.x + bb.x, 0.f);
            v.y = fmaxf(v.y + bb.y, 0.f);
            v.z = fmaxf(v.z + bb.z, 0.f);
            v.w = fmaxf(v.w + bb.w, 0.f);
            *(float4*)(C + (size_t)gm * N + gn) = v;
        }
    }
}

// ---------------------------------------------------------------------------
// Final layer: out[e] = dot(h2[e, 0:256], W3) + b3   (N = 1), fp32.
// One warp per edge, fully-coalesced float4 reads, shfl reduction.
// ---------------------------------------------------------------------------
__global__ __launch_bounds__(256)
void out_kernel(const float* __restrict__ W3, const float* __restrict__ b3,
                float* __restrict__ out)
{
    const int warp = threadIdx.x >> 5;
    const int lane = threadIdx.x & 31;
    const int e = blockIdx.x * 8 + warp;
    if (e >= kEdges) return;
    const float4* row = (const float4*)(g_h2 + (size_t)e * 256);
    const float4* w = (const float4*)W3;
    float s = 0.f;
#pragma unroll
    for (int i = 0; i < 2; ++i) {
        float4 a = row[lane + i * 32];
        float4 b = w[lane + i * 32];
        s += a.x * b.x + a.y * b.y + a.z * b.z + a.w * b.w;
    }
#pragma unroll
    for (int o = 16; o; o >>= 1) s += __shfl_xor_sync(0xffffffffu, s, o);
    if (lane == 0) out[e] = s + b3[0];
}

// ---------------------------------------------------------------------------
extern "C" void kernel_launch(void* const* d_in, const int* in_sizes, int n_in,
                              void* d_out, int out_size)
{
    const float* x     = (const float*)d_in[0];
    const void*  eidx  = d_in[1];
    const float* eattr = (const float*)d_in[2];
    const float* Wn    = (const float*)d_in[3];
    const float* bnode = (const float*)d_in[4];
    const float* We    = (const float*)d_in[5];
    const float* be    = (const float*)d_in[6];
    const float* W1    = (const float*)d_in[7];
    const float* b1    = (const float*)d_in[8];
    const float* W2    = (const float*)d_in[9];
    const float* b2    = (const float*)d_in[10];
    const float* W3    = (const float*)d_in[11];
    const float* b3    = (const float*)d_in[12];
    float* out = (float*)d_out;

    float *p_node, *p_edge, *p_h1, *p_h2;
    cudaGetSymbolAddress((void**)&p_node, g_node_f);
    cudaGetSymbolAddress((void**)&p_edge, g_edge_f);
    cudaGetSymbolAddress((void**)&p_h1, g_h1);
    cudaGetSymbolAddress((void**)&p_h2, g_h2);

    // Normalize edge_index into int32 scratch (handles int32 or int64 input)
    detect_idx_kernel<<<1, 32>>>(eidx);
    conv_idx_kernel<<<(kEdges + 255) / 256, 256>>>(eidx);

    // node_f = relu(x @ Wn + bn)            [50000, 128]
    gemm_bias_kernel<true><<<dim3((kNodes + BM - 1) / BM, 128 / BN), NTHREADS>>>(
        x, Wn, bnode, p_node, kNodes, 128, 128);

    // edge_f = relu(edge_attr @ We + be)    [500000, 128]
    gemm_bias_kernel<true><<<dim3((kEdges + BM - 1) / BM, 128 / BN), NTHREADS>>>(
        eattr, We, be, p_edge, kEdges, 128, 64);

    // h1 = relu(concat(node_f[src], node_f[dst], edge_f) @ W1 + b1)  [500000, 512]
    gemm_gather_kernel<<<dim3((kEdges + BM - 1) / BM, 512 / BN), NTHREADS>>>(
        W1, b1, p_h1);

    // h2 = relu(h1 @ W2 + b2)               [500000, 256]
    gemm_bias_kernel<true><<<dim3((kEdges + BM - 1) / BM, 256 / BN), NTHREADS>>>(
        p_h1, W2, b2, p_h2, kEdges, 256, 512);

    // out = h2 @ W3 + b3                    [500000, 1]
    out_kernel<<<(kEdges + 7) / 8, 256>>>(W3, b3, out);
}

// round 2
// speedup vs baseline: 1.8879x; 1.8879x over previous
#include <cuda_runtime.h>
#include <mma.h>
#include <cstdint>

using namespace nvcuda;

namespace {
constexpr int kNodes = 50000;
constexpr int kEdges = 500000;
constexpr int BM = 128, BN = 128, BK = 16;
constexpr int BKP = 20;    // padded A ldm
constexpr int BNP = 132;   // padded B ldm
constexpr int NTHREADS = 256;
// weight scratch offsets (floats)
constexpr int OFF_WN = 0;                  // 128*128
constexpr int OFF_WE = 16384;              // 64*128
constexpr int OFF_W1 = 16384 + 8192;       // 384*512
constexpr int OFF_W2 = OFF_W1 + 196608;    // 512*256
constexpr int WT_TOTAL = OFF_W2 + 131072;
}

// Static scratch (allocation-free rule: __device__ globals)
__device__ float g_node_f[(size_t)kNodes * 128];
__device__ float g_edge_f[(size_t)kEdges * 128];
__device__ float g_h1[(size_t)kEdges * 512];
__device__ float g_h2[(size_t)kEdges * 256];
__device__ float g_xt[(size_t)kNodes * 128];
__device__ float g_eat[(size_t)kEdges * 64];
__device__ float g_wt[WT_TOTAL];
__device__ int   g_src[kEdges];
__device__ int   g_dst[kEdges];
__device__ int   g_is64;

__device__ __forceinline__ float tf32_rn(float x) {
    uint32_t u;
    asm("cvt.rna.tf32.f32 %0, %1;" : "=r"(u) : "f"(x));
    return __uint_as_float(u);
}

__device__ __forceinline__ void cp_async16(void* smem, const void* gmem) {
    uint32_t s = (uint32_t)__cvta_generic_to_shared(smem);
    asm volatile("cp.async.cg.shared.global [%0], [%1], 16;\n" :: "r"(s), "l"(gmem));
}
__device__ __forceinline__ void cp_commit() {
    asm volatile("cp.async.commit_group;\n");
}
__device__ __forceinline__ void cp_wait1() {
    asm volatile("cp.async.wait_group 1;\n");
}

// ---------------------------------------------------------------------------
// edge_index dtype detection (int64 vs int32)
// ---------------------------------------------------------------------------
__global__ void detect_idx_kernel(const void* idx) {
    if (threadIdx.x == 0 && blockIdx.x == 0) {
        const long long* p = (const long long*)idx;
        int ok = 1;
        for (int i = 0; i < 256; ++i) {
            long long v = p[i];
            if (v < 0 || v >= kNodes) { ok = 0; break; }
        }
        g_is64 = ok;
    }
}

__global__ void conv_idx_kernel(const void* idx) {
    int i = blockIdx.x * blockDim.x + threadIdx.x;
    if (i >= kEdges) return;
    int s, d;
    if (g_is64) {
        const long long* p = (const long long*)idx;
        s = (int)p[i];
        d = (int)p[kEdges + i];
    } else {
        const int* p = (const int*)idx;
        s = p[i];
        d = p[kEdges + i];
    }
    g_src[i] = s;
    g_dst[i] = d;
}

// ---------------------------------------------------------------------------
// Pre-round fp32 -> tf32-representable fp32 (RN), float4 vectorized.
// ---------------------------------------------------------------------------
__global__ void round_kernel(const float* __restrict__ src, float* __restrict__ dst, int n4) {
    int i = blockIdx.x * blockDim.x + threadIdx.x;
    if (i >= n4) return;
    float4 v = ((const float4*)src)[i];
    v.x = tf32_rn(v.x); v.y = tf32_rn(v.y);
    v.z = tf32_rn(v.z); v.w = tf32_rn(v.w);
    ((float4*)dst)[i] = v;
}

// ---------------------------------------------------------------------------
// TF32 wmma GEMM, 128x128x16 block tile, 8 warps (64x32 warp tile), 2-stage
// cp.async pipeline. Inputs must already be tf32-rounded fp32.
// C[M,N] = act(A[M,K] @ B[K,N] + bias[N]) ; act = relu if RELU;
// output re-rounded to tf32 if ROUND (when C feeds another GEMM).
// GATHER: A row e = concat(node_f[src[e]], node_f[dst[e]], edge_f[e]), K=384.
// Requirements: N % 128 == 0, K % 16 == 0 (all layers satisfy).
// ---------------------------------------------------------------------------
template <bool RELU, bool ROUND, bool GATHER>
__global__ __launch_bounds__(NTHREADS, 2)
void gemm_kernel(const float* __restrict__ A, const float* __restrict__ B,
                 const float* __restrict__ bias, float* __restrict__ C,
                 int M, int N, int K)
{
    __shared__ float sA[2][BM][BKP];
    __shared__ float sB[2][BK][BNP];
    __shared__ float sSt[8][16][20];
    __shared__ int sSrc[BM], sDst[BM];

    const int bm = blockIdx.x * BM;
    const int bn = blockIdx.y * BN;
    const int tid = threadIdx.x;
    const int warp = tid >> 5;
    const int lane = tid & 31;
    const int wm = (warp >> 2) * 64;   // 2 warps in M
    const int wn = (warp & 3) * 32;    // 4 warps in N

    if (GATHER) {
        if (tid < BM) {
            int e = min(bm + tid, M - 1);
            sSrc[tid] = g_src[e];
            sDst[tid] = g_dst[e];
        }
        __syncthreads();
    }

    wmma::fragment<wmma::accumulator, 16, 16, 8, float> acc[4][2];
#pragma unroll
    for (int i = 0; i < 4; ++i)
#pragma unroll
        for (int j = 0; j < 2; ++j) wmma::fill_fragment(acc[i][j], 0.0f);

    auto load_stage = [&](int buf, int k0) {
        // A tile: 128 rows x 16 floats = 512 float4
#pragma unroll
        for (int t = 0; t < 2; ++t) {
            int f4 = tid + t * NTHREADS;
            int r = f4 >> 2, c = (f4 & 3) * 4;
            const float* src;
            if (GATHER) {
                int seg = k0 >> 7;
                int koff = (k0 & 127) + c;
                int e = min(bm + r, M - 1);
                if (seg == 0)      src = g_node_f + (size_t)sSrc[r] * 128 + koff;
                else if (seg == 1) src = g_node_f + (size_t)sDst[r] * 128 + koff;
                else               src = g_edge_f + (size_t)e * 128 + koff;
            } else {
                int gm = min(bm + r, M - 1);
                src = A + (size_t)gm * K + k0 + c;
            }
            cp_async16(&sA[buf][r][c], src);
        }
        // B tile: 16 rows x 128 floats = 512 float4
#pragma unroll
        for (int t = 0; t < 2; ++t) {
            int f4 = tid + t * NTHREADS;
            int r = f4 >> 5, c = (f4 & 31) * 4;
            cp_async16(&sB[buf][r][c], B + (size_t)(k0 + r) * N + bn + c);
        }
    };

    const int nk = K >> 4;
    load_stage(0, 0);
    cp_commit();

    for (int it = 0; it < nk; ++it) {
        if (it + 1 < nk) load_stage((it + 1) & 1, (it + 1) << 4);
        cp_commit();
        cp_wait1();
        __syncthreads();

        const int buf = it & 1;
#pragma unroll
        for (int kk = 0; kk < BK; kk += 8) {
            wmma::fragment<wmma::matrix_a, 16, 16, 8, wmma::precision::tf32, wmma::row_major> a[4];
            wmma::fragment<wmma::matrix_b, 16, 16, 8, wmma::precision::tf32, wmma::row_major> b[2];
#pragma unroll
            for (int m = 0; m < 4; ++m)
                wmma::load_matrix_sync(a[m], &sA[buf][wm + m * 16][kk], BKP);
#pragma unroll
            for (int j = 0; j < 2; ++j)
                wmma::load_matrix_sync(b[j], &sB[buf][kk][wn + j * 16], BNP);
#pragma unroll
            for (int m = 0; m < 4; ++m)
#pragma unroll
                for (int j = 0; j < 2; ++j)
                    wmma::mma_sync(acc[m][j], a[m], b[j], acc[m][j]);
        }
        __syncthreads();
    }

    // Epilogue: frag -> per-warp shared staging -> bias+relu(+round) -> global
    const int r = lane >> 1;
    const int cb = (lane & 1) * 8;
#pragma unroll
    for (int i = 0; i < 4; ++i) {
#pragma unroll
        for (int j = 0; j < 2; ++j) {
            wmma::store_matrix_sync(&sSt[warp][0][0], acc[i][j], 20, wmma::mem_row_major);
            __syncwarp();
            int gm = bm + wm + i * 16 + r;
            int gn = bn + wn + j * 16 + cb;
            if (gm < M) {
                float4 v0 = *(float4*)&sSt[warp][r][cb];
                float4 v1 = *(float4*)&sSt[warp][r][cb + 4];
                float4 bb0 = __ldg((const float4*)(bias + gn));
                float4 bb1 = __ldg((const float4*)(bias + gn + 4));
                v0.x += bb0.x; v0.y += bb0.y; v0.z += bb0.z; v0.w += bb0.w;
                v1.x += bb1.x; v1.y += bb1.y; v1.z += bb1.z; v1.w += bb1.w;
                if (RELU) {
                    v0.x = fmaxf(v0.x, 0.f); v0.y = fmaxf(v0.y, 0.f);
                    v0.z = fmaxf(v0.z, 0.f); v0.w = fmaxf(v0.w, 0.f);
                    v1.x = fmaxf(v1.x, 0.f); v1.y = fmaxf(v1.y, 0.f);
                    v1.z = fmaxf(v1.z, 0.f); v1.w = fmaxf(v1.w, 0.f);
                }
                if (ROUND) {
                    v0.x = tf32_rn(v0.x); v0.y = tf32_rn(v0.y);
                    v0.z = tf32_rn(v0.z); v0.w = tf32_rn(v0.w);
                    v1.x = tf32_rn(v1.x); v1.y = tf32_rn(v1.y);
                    v1.z = tf32_rn(v1.z); v1.w = tf32_rn(v1.w);
                }
                *(float4*)(C + (size_t)gm * N + gn) = v0;
                *(float4*)(C + (size_t)gm * N + gn + 4) = v1;
            }
            __syncwarp();
        }
    }
}

// ---------------------------------------------------------------------------
// Final layer: out[e] = dot(h2[e, 0:256], W3) + b3   (N = 1), fp32.
// ---------------------------------------------------------------------------
__global__ __launch_bounds__(256)
void out_kernel(const float* __restrict__ W3, const float* __restrict__ b3,
                float* __restrict__ out)
{
    const int warp = threadIdx.x >> 5;
    const int lane = threadIdx.x & 31;
    const int e = blockIdx.x * 8 + warp;
    if (e >= kEdges) return;
    const float4* row = (const float4*)(g_h2 + (size_t)e * 256);
    const float4* w = (const float4*)W3;
    float s = 0.f;
#pragma unroll
    for (int i = 0; i < 2; ++i) {
        float4 a = row[lane + i * 32];
        float4 b = w[lane + i * 32];
        s += a.x * b.x + a.y * b.y + a.z * b.z + a.w * b.w;
    }
#pragma unroll
    for (int o = 16; o; o >>= 1) s += __shfl_xor_sync(0xffffffffu, s, o);
    if (lane == 0) out[e] = s + b3[0];
}

// ---------------------------------------------------------------------------
extern "C" void kernel_launch(void* const* d_in, const int* in_sizes, int n_in,
                              void* d_out, int out_size)
{
    const float* x     = (const float*)d_in[0];
    const void*  eidx  = d_in[1];
    const float* eattr = (const float*)d_in[2];
    const float* Wn    = (const float*)d_in[3];
    const float* bnode = (const float*)d_in[4];
    const float* We    = (const float*)d_in[5];
    const float* be    = (const float*)d_in[6];
    const float* W1    = (const float*)d_in[7];
    const float* b1    = (const float*)d_in[8];
    const float* W2    = (const float*)d_in[9];
    const float* b2    = (const float*)d_in[10];
    const float* W3    = (const float*)d_in[11];
    const float* b3    = (const float*)d_in[12];
    float* out = (float*)d_out;

    float *p_node, *p_edge, *p_h1, *p_h2, *p_xt, *p_eat, *p_wt;
    cudaGetSymbolAddress((void**)&p_node, g_node_f);
    cudaGetSymbolAddress((void**)&p_edge, g_edge_f);
    cudaGetSymbolAddress((void**)&p_h1, g_h1);
    cudaGetSymbolAddress((void**)&p_h2, g_h2);
    cudaGetSymbolAddress((void**)&p_xt, g_xt);
    cudaGetSymbolAddress((void**)&p_eat, g_eat);
    cudaGetSymbolAddress((void**)&p_wt, g_wt);

    // Normalize edge_index into int32 scratch (handles int32 or int64 input)
    detect_idx_kernel<<<1, 32>>>(eidx);
    conv_idx_kernel<<<(kEdges + 255) / 256, 256>>>(eidx);

    // Pre-round all GEMM inputs to tf32-representable fp32 (RN)
    auto rnd = [](const float* s, float* d, int n) {
        round_kernel<<<(n / 4 + 255) / 256, 256>>>(s, d, n / 4);
    };
    rnd(x, p_xt, kNodes * 128);
    rnd(eattr, p_eat, kEdges * 64);
    rnd(Wn, p_wt + OFF_WN, 128 * 128);
    rnd(We, p_wt + OFF_WE, 64 * 128);
    rnd(W1, p_wt + OFF_W1, 384 * 512);
    rnd(W2, p_wt + OFF_W2, 512 * 256);

    // node_f = relu(x @ Wn + bn)   [50000, 128]  (rounded -> feeds W1)
    gemm_kernel<true, true, false><<<dim3((kNodes + BM - 1) / BM, 1), NTHREADS>>>(
        p_xt, p_wt + OFF_WN, bnode, p_node, kNodes, 128, 128);

    // edge_f = relu(edge_attr @ We + be)   [500000, 128]  (rounded)
    gemm_kernel<true, true, false><<<dim3((kEdges + BM - 1) / BM, 1), NTHREADS>>>(
        p_eat, p_wt + OFF_WE, be, p_edge, kEdges, 128, 64);

    // h1 = relu(concat(node_f[src], node_f[dst], edge_f) @ W1 + b1)  [500000, 512]
    gemm_kernel<true, true, true><<<dim3((kEdges + BM - 1) / BM, 4), NTHREADS>>>(
        nullptr, p_wt + OFF_W1, b1, p_h1, kEdges, 512, 384);

    // h2 = relu(h1 @ W2 + b2)   [500000, 256]  (fp32 out, feeds fp32 dot)
    gemm_kernel<true, false, false><<<dim3((kEdges + BM - 1) / BM, 2), NTHREADS>>>(
        p_h1, p_wt + OFF_W2, b2, p_h2, kEdges, 256, 512);

    // out = h2 @ W3 + b3   [500000, 1]
    out_kernel<<<(kEdges + 7) / 8, 256>>>(W3, b3, out);
}

// round 5
// speedup vs baseline: 3.1849x; 1.6870x over previous
#include <cuda_runtime.h>
#include <cstdint>

namespace {
constexpr int kNodes = 50000;
constexpr int kEdges = 500000;
constexpr int SMEM_BYTES = 67584;   // A 32K | B 32K | bias 512 | w3 512 | src 512 | dst 512 (+pad)
}

// ============================================================================
// Static device scratch (allocation-free rule)
// ============================================================================
__device__ float g_node_f[(size_t)kNodes * 128];
__device__ float g_edge_f[(size_t)kEdges * 128];
__device__ float g_h1[(size_t)kEdges * 512];
__device__ float g_xt[(size_t)kNodes * 128];
__device__ float g_eat[(size_t)kEdges * 64];
__device__ float g_wnt[128 * 128];
__device__ float g_wet[128 * 64];
__device__ float g_w1t[512 * 384];
__device__ float g_w2t[256 * 512];
__device__ int   g_src[kEdges];
__device__ int   g_dst[kEdges];
__device__ int   g_is64;

// ============================================================================
// Helpers
// ============================================================================
__device__ __forceinline__ float tf32_rn(float x) {
    uint32_t u;
    asm("cvt.rna.tf32.f32 %0, %1;" : "=r"(u) : "f"(x));
    return __uint_as_float(u);
}
__device__ __forceinline__ void cp_async16(void* smem, const void* gmem) {
    uint32_t s;
    asm("{ .reg .u64 t; cvta.to.shared.u64 t, %1; cvt.u32.u64 %0, t; }" : "=r"(s) : "l"(smem));
    asm volatile("cp.async.cg.shared.global [%0], [%1], 16;\n" :: "r"(s), "l"(gmem));
}
__device__ __forceinline__ void cp_commit() { asm volatile("cp.async.commit_group;\n"); }
__device__ __forceinline__ void cp_wait0()  { asm volatile("cp.async.wait_group 0;\n" ::: "memory"); }
__device__ __forceinline__ void cp_wait1()  { asm volatile("cp.async.wait_group 1;\n" ::: "memory"); }

// mma.sync m16n8k8 tf32: d += a*b  (c aliased with d)
__device__ __forceinline__ void mma1688(float* c, const uint32_t* a, const uint32_t* b) {
    asm volatile(
        "mma.sync.aligned.m16n8k8.row.col.f32.tf32.tf32.f32 "
        "{%0,%1,%2,%3}, {%4,%5,%6,%7}, {%8,%9}, {%0,%1,%2,%3};"
        : "+f"(c[0]), "+f"(c[1]), "+f"(c[2]), "+f"(c[3])
        : "r"(a[0]), "r"(a[1]), "r"(a[2]), "r"(a[3]), "r"(b[0]), "r"(b[1]));
}

// ============================================================================
// Prep kernels
// ============================================================================
__global__ void detect_idx_kernel(const void* idx) {
    if (threadIdx.x == 0 && blockIdx.x == 0) {
        const long long* p = (const long long*)idx;
        int ok = 1;
        for (int i = 0; i < 256; ++i) {
            long long v = p[i];
            if (v < 0 || v >= kNodes) { ok = 0; break; }
        }
        g_is64 = ok;
    }
}
__global__ void conv_idx_kernel(const void* idx) {
    int i = blockIdx.x * blockDim.x + threadIdx.x;
    if (i >= kEdges) return;
    int s, d;
    if (g_is64) {
        const long long* p = (const long long*)idx;
        s = (int)p[i]; d = (int)p[kEdges + i];
    } else {
        const int* p = (const int*)idx;
        s = p[i]; d = p[kEdges + i];
    }
    g_src[i] = s; g_dst[i] = d;
}
__global__ void round_kernel(const float* __restrict__ src, float* __restrict__ dst, int n4) {
    int i = blockIdx.x * blockDim.x + threadIdx.x;
    if (i >= n4) return;
    float4 v = ((const float4*)src)[i];
    v.x = tf32_rn(v.x); v.y = tf32_rn(v.y); v.z = tf32_rn(v.z); v.w = tf32_rn(v.w);
    ((float4*)dst)[i] = v;
}
// Transpose + round + k-pair-interleave: W[k][n] (KxN row-major) ->
// Bt[n][ (k>>3)*8 + 2*(k&3) + ((k&4)>>2) ]   so a thread's (k, k+4) mma B pair
// is contiguous (one LDS.64) while gmem->smem copies stay 16B-chunk identical.
__global__ void trans_round_kernel(const float* __restrict__ W, float* __restrict__ Bt,
                                   int K, int N) {
    int i = blockIdx.x * blockDim.x + threadIdx.x;
    if (i >= K * N) return;
    int k = i / N, n = i % N;
    int pos = (k >> 3) * 8 + 2 * (k & 3) + ((k & 4) >> 2);
    Bt[(size_t)n * K + pos] = tf32_rn(W[(size_t)k * N + n]);
}
__global__ void init_out_kernel(float* __restrict__ out, const float* __restrict__ b3) {
    int i = blockIdx.x * blockDim.x + threadIdx.x;
    if (i < kEdges) out[i] = b3[0];
}

// ============================================================================
// TF32 mma.sync GEMM.  C[M,N] = relu(A[M,K] @ Bt[N,K]^T + bias)
//   EPI=0 : store C rounded to tf32 (feeds next GEMM)
//   EPI=1 : fused dot with W3: atomicAdd partial of out[m] (out pre-init b3)
//   GATHER: A row e = concat(node_f[src[e]], node_f[dst[e]], edge_f[e])
// CTA tile 128x128, BK=32, 8 warps (2M x 4N), warp tile 64x32 (4x4 m16n8).
// grid = (N/128, ceil(M/128))  -- N-blocks adjacent for L2 reuse of A.
// ============================================================================
template <int K, int N, int EPI, bool GATHER>
__global__ __launch_bounds__(256, 2)
void mm_kernel(const float* __restrict__ A, const float* __restrict__ Bt,
               const float* __restrict__ bias, float* __restrict__ Cmat,
               const float* __restrict__ W3, float* __restrict__ outv, int M)
{
    constexpr int NS = K / 32;
    extern __shared__ float smf[];
    float* sAf   = smf;             // 2 x 4096 floats
    float* sBf   = smf + 8192;      // 2 x 4096 floats
    float* sBias = smf + 16384;     // 128
    float* sW3   = smf + 16512;     // 128
    int*   sSrc  = (int*)(smf + 16640);
    int*   sDst  = (int*)(smf + 16768);

    const int tid  = threadIdx.x;
    const int lane = tid & 31;
    const int warp = tid >> 5;
    const int r    = lane >> 2;      // 0..7
    const int c    = lane & 3;       // 0..3
    const int wm   = (warp >> 2) * 64;
    const int wnl  = (warp & 3) * 32;
    const int bn   = blockIdx.x * 128;
    const int bm   = blockIdx.y * 128;

    if (tid < 128) sBias[tid] = __ldg(bias + bn + tid);
    if (EPI == 1 && tid < 128) sW3[tid] = __ldg(W3 + bn + tid);
    if (GATHER && tid < 128) {
        int e = min(bm + tid, M - 1);
        sSrc[tid] = g_src[e];
        sDst[tid] = g_dst[e];
    }
    __syncthreads();

    // ---- stage loader: A swizzle col^(row&4); B already gmem-permuted ----
    auto load_stage = [&](int s) {
        const int buf = s & 1;
        const int k0 = s * 32;
        float* dA = sAf + buf * 4096;
        float* dB = sBf + buf * 4096;
#pragma unroll
        for (int t = 0; t < 4; ++t) {
            int idx = tid + t * 256;
            int row = idx >> 3, c4 = idx & 7;
            int kk = c4 * 4;
            int slice = kk >> 3, colb = kk & 7;
            float* dst = dA + slice * 1024 + row * 8 + (colb ^ (row & 4));
            const float* src;
            if (GATHER) {
                int koff = (k0 & 127) + kk;
                if (k0 < 128)      src = g_node_f + (size_t)sSrc[row] * 128 + koff;
                else if (k0 < 256) src = g_node_f + (size_t)sDst[row] * 128 + koff;
                else               src = g_edge_f + (size_t)min(bm + row, M - 1) * 128 + koff;
            } else {
                src = A + (size_t)min(bm + row, M - 1) * K + k0 + kk;
            }
            cp_async16(dst, src);
        }
#pragma unroll
        for (int t = 0; t < 4; ++t) {
            int idx = tid + t * 256;
            int n = idx >> 3, c4 = idx & 7;
            float* dst = dB + (c4 >> 1) * 1024 + n * 8 + (c4 & 1) * 4;
            cp_async16(dst, Bt + (size_t)(bn + n) * K + k0 + c4 * 4);
        }
    };

    float cf[4][4][4] = {};

    load_stage(0); cp_commit();
    load_stage(1); cp_commit();

    for (int s = 0; s < NS; ++s) {
        if (s + 1 < NS) cp_wait1(); else cp_wait0();
        __syncthreads();
        const float* fA = sAf + (s & 1) * 4096;
        const float* fB = sBf + (s & 1) * 4096;
#pragma unroll
        for (int k8 = 0; k8 < 4; ++k8) {
            uint32_t av[4][4];
#pragma unroll
            for (int ma = 0; ma < 4; ++ma) {
                const int rowa = wm + ma * 16 + r;
                const int r4 = rowa & 4;
                const float* pa = fA + k8 * 1024 + rowa * 8;
                av[ma][0] = __float_as_uint(pa[c ^ r4]);
                av[ma][1] = __float_as_uint(pa[64 + (c ^ r4)]);
                av[ma][2] = __float_as_uint(pa[(c + 4) ^ r4]);
                av[ma][3] = __float_as_uint(pa[64 + ((c + 4) ^ r4)]);
            }
            uint32_t bv[4][2];
#pragma unroll
            for (int na = 0; na < 4; ++na) {
                const float2 t2 = *(const float2*)(fB + k8 * 1024 + (wnl + na * 8 + r) * 8 + 2 * c);
                bv[na][0] = __float_as_uint(t2.x);
                bv[na][1] = __float_as_uint(t2.y);
            }
#pragma unroll
            for (int ma = 0; ma < 4; ++ma)
#pragma unroll
                for (int na = 0; na < 4; ++na)
                    mma1688(cf[ma][na], av[ma], bv[na]);
        }
        __syncthreads();
        if (s + 2 < NS) { load_stage(s + 2); cp_commit(); }
    }

    // ---- epilogue ----
    float2 bias2[4];
#pragma unroll
    for (int na = 0; na < 4; ++na)
        bias2[na] = *(const float2*)&sBias[wnl + na * 8 + 2 * c];

    if (EPI == 0) {
#pragma unroll
        for (int ma = 0; ma < 4; ++ma) {
            const int row0 = bm + wm + ma * 16 + r;
            const int row1 = row0 + 8;
#pragma unroll
            for (int na = 0; na < 4; ++na) {
                const int col = bn + wnl + na * 8 + 2 * c;
                if (row0 < M) {
                    float2 v;
                    v.x = tf32_rn(fmaxf(cf[ma][na][0] + bias2[na].x, 0.f));
                    v.y = tf32_rn(fmaxf(cf[ma][na][1] + bias2[na].y, 0.f));
                    *(float2*)(Cmat + (size_t)row0 * N + col) = v;
                }
                if (row1 < M) {
                    float2 v;
                    v.x = tf32_rn(fmaxf(cf[ma][na][2] + bias2[na].x, 0.f));
                    v.y = tf32_rn(fmaxf(cf[ma][na][3] + bias2[na].y, 0.f));
                    *(float2*)(Cmat + (size_t)row1 * N + col) = v;
                }
            }
        }
    } else {
        float2 w3v[4];
#pragma unroll
        for (int na = 0; na < 4; ++na)
            w3v[na] = *(const float2*)&sW3[wnl + na * 8 + 2 * c];
        float* psum = sAf;                       // sA dead after final sync
#pragma unroll
        for (int ma = 0; ma < 4; ++ma) {
            float p0 = 0.f, p1 = 0.f;
#pragma unroll
            for (int na = 0; na < 4; ++na) {
                p0 += fmaxf(cf[ma][na][0] + bias2[na].x, 0.f) * w3v[na].x
                    + fmaxf(cf[ma][na][1] + bias2[na].y, 0.f) * w3v[na].y;
                p1 += fmaxf(cf[ma][na][2] + bias2[na].x, 0.f) * w3v[na].x
                    + fmaxf(cf[ma][na][3] + bias2[na].y, 0.f) * w3v[na].y;
            }
            p0 += __shfl_xor_sync(0xffffffffu, p0, 1);
            p0 += __shfl_xor_sync(0xffffffffu, p0, 2);
            p1 += __shfl_xor_sync(0xffffffffu, p1, 1);
            p1 += __shfl_xor_sync(0xffffffffu, p1, 2);
            if (c == 0) {
                const int rl = wm + ma * 16 + r;
                psum[rl * 4 + (warp & 3)] = p0;
                psum[(rl + 8) * 4 + (warp & 3)] = p1;
            }
        }
        __syncthreads();
        if (tid < 128) {
            const int gm = bm + tid;
            if (gm < M)
                atomicAdd(outv + gm,
                          psum[tid * 4] + psum[tid * 4 + 1] + psum[tid * 4 + 2] + psum[tid * 4 + 3]);
        }
    }
}

// ============================================================================
extern "C" void kernel_launch(void* const* d_in, const int* in_sizes, int n_in,
                              void* d_out, int out_size)
{
    const float* x     = (const float*)d_in[0];
    const void*  eidx  = d_in[1];
    const float* eattr = (const float*)d_in[2];
    const float* Wn    = (const float*)d_in[3];
    const float* bnode = (const float*)d_in[4];
    const float* We    = (const float*)d_in[5];
    const float* be    = (const float*)d_in[6];
    const float* W1    = (const float*)d_in[7];
    const float* b1    = (const float*)d_in[8];
    const float* W2    = (const float*)d_in[9];
    const float* b2    = (const float*)d_in[10];
    const float* W3    = (const float*)d_in[11];
    const float* b3    = (const float*)d_in[12];
    float* out = (float*)d_out;

    float *p_node, *p_edge, *p_h1, *p_xt, *p_eat, *p_wnt, *p_wet, *p_w1t, *p_w2t;
    cudaGetSymbolAddress((void**)&p_node, g_node_f);
    cudaGetSymbolAddress((void**)&p_edge, g_edge_f);
    cudaGetSymbolAddress((void**)&p_h1, g_h1);
    cudaGetSymbolAddress((void**)&p_xt, g_xt);
    cudaGetSymbolAddress((void**)&p_eat, g_eat);
    cudaGetSymbolAddress((void**)&p_wnt, g_wnt);
    cudaGetSymbolAddress((void**)&p_wet, g_wet);
    cudaGetSymbolAddress((void**)&p_w1t, g_w1t);
    cudaGetSymbolAddress((void**)&p_w2t, g_w2t);

    detect_idx_kernel<<<1, 32>>>(eidx);
    conv_idx_kernel<<<(kEdges + 255) / 256, 256>>>(eidx);
    init_out_kernel<<<(kEdges + 255) / 256, 256>>>(out, b3);

    round_kernel<<<(kNodes * 32 + 255) / 256, 256>>>(x, p_xt, kNodes * 32);
    round_kernel<<<(kEdges * 16 + 255) / 256, 256>>>(eattr, p_eat, kEdges * 16);
    trans_round_kernel<<<(128 * 128 + 255) / 256, 256>>>(Wn, p_wnt, 128, 128);
    trans_round_kernel<<<(64 * 128 + 255) / 256, 256>>>(We, p_wet, 64, 128);
    trans_round_kernel<<<(384 * 512 + 255) / 256, 256>>>(W1, p_w1t, 384, 512);
    trans_round_kernel<<<(512 * 256 + 255) / 256, 256>>>(W2, p_w2t, 512, 256);

    // node encoder [50000,128]
    cudaFuncSetAttribute(mm_kernel<128, 128, 0, false>,
                         cudaFuncAttributeMaxDynamicSharedMemorySize, SMEM_BYTES);
    mm_kernel<128, 128, 0, false><<<dim3(1, (kNodes + 127) / 128), 256, SMEM_BYTES>>>(
        p_xt, p_wnt, bnode, p_node, nullptr, nullptr, kNodes);

    // edge encoder [500000,128]
    cudaFuncSetAttribute(mm_kernel<64, 128, 0, false>,
                         cudaFuncAttributeMaxDynamicSharedMemorySize, SMEM_BYTES);
    mm_kernel<64, 128, 0, false><<<dim3(1, (kEdges + 127) / 128), 256, SMEM_BYTES>>>(
        p_eat, p_wet, be, p_edge, nullptr, nullptr, kEdges);

    // W1 gather-fused: [500000,512]
    cudaFuncSetAttribute(mm_kernel<384, 512, 0, true>,
                         cudaFuncAttributeMaxDynamicSharedMemorySize, SMEM_BYTES);
    mm_kernel<384, 512, 0, true><<<dim3(4, (kEdges + 127) / 128), 256, SMEM_BYTES>>>(
        nullptr, p_w1t, b1, p_h1, nullptr, nullptr, kEdges);

    // W2 + fused final dot
    cudaFuncSetAttribute(mm_kernel<512, 256, 1, false>,
                         cudaFuncAttributeMaxDynamicSharedMemorySize, SMEM_BYTES);
    mm_kernel<512, 256, 1, false><<<dim3(2, (kEdges + 127) / 128), 256, SMEM_BYTES>>>(
        p_h1, p_w2t, b2, nullptr, W3, out, kEdges);
}

// round 6
// speedup vs baseline: 3.2139x; 1.0091x over previous
#include <cuda_runtime.h>
#include <cstdint>

namespace {
constexpr int kNodes = 50000;
constexpr int kEdges = 500000;
// floats: sA 3*4096 | sB 3*4096 | bias 128 | w3 128 | src 128 | dst 128
constexpr int SMEM_BYTES = (24576 + 512) * 4;   // 100352
}

// ============================================================================
// Static device scratch (allocation-free rule)
// All activation matrices stored K-PERMUTED: pos(k) = (k&~7)+2*(k&3)+((k&4)>>2)
// ============================================================================
__device__ float g_node_f[(size_t)kNodes * 128];
__device__ float g_edge_f[(size_t)kEdges * 128];
__device__ float g_h1[(size_t)kEdges * 512];
__device__ float g_xt[(size_t)kNodes * 128];
__device__ float g_eat[(size_t)kEdges * 64];
__device__ float g_wnt[128 * 128];
__device__ float g_wet[128 * 64];
__device__ float g_w1t[512 * 384];
__device__ float g_w2t[256 * 512];
__device__ int   g_src[kEdges];
__device__ int   g_dst[kEdges];
__device__ int   g_is64;

// ============================================================================
// Helpers
// ============================================================================
__device__ __forceinline__ float tf32_rn(float x) {
    uint32_t u;
    asm("cvt.rna.tf32.f32 %0, %1;" : "=r"(u) : "f"(x));
    return __uint_as_float(u);
}
__device__ __forceinline__ void cp_async16(void* smem, const void* gmem) {
    uint32_t s;
    asm("{ .reg .u64 t; cvta.to.shared.u64 t, %1; cvt.u32.u64 %0, t; }" : "=r"(s) : "l"(smem));
    asm volatile("cp.async.cg.shared.global [%0], [%1], 16;\n" :: "r"(s), "l"(gmem));
}
__device__ __forceinline__ void cp_commit() { asm volatile("cp.async.commit_group;\n"); }
__device__ __forceinline__ void cp_wait0()  { asm volatile("cp.async.wait_group 0;\n" ::: "memory"); }
__device__ __forceinline__ void cp_wait1()  { asm volatile("cp.async.wait_group 1;\n" ::: "memory"); }

__device__ __forceinline__ void mma1688(float* c, const uint32_t* a, const uint32_t* b) {
    asm volatile(
        "mma.sync.aligned.m16n8k8.row.col.f32.tf32.tf32.f32 "
        "{%0,%1,%2,%3}, {%4,%5,%6,%7}, {%8,%9}, {%0,%1,%2,%3};"
        : "+f"(c[0]), "+f"(c[1]), "+f"(c[2]), "+f"(c[3])
        : "r"(a[0]), "r"(a[1]), "r"(a[2]), "r"(a[3]), "r"(b[0]), "r"(b[1]));
}

// ============================================================================
// Prep kernels
// ============================================================================
__global__ void detect_idx_kernel(const void* idx) {
    if (threadIdx.x == 0 && blockIdx.x == 0) {
        const long long* p = (const long long*)idx;
        int ok = 1;
        for (int i = 0; i < 256; ++i) {
            long long v = p[i];
            if (v < 0 || v >= kNodes) { ok = 0; break; }
        }
        g_is64 = ok;
    }
}
__global__ void conv_idx_kernel(const void* idx) {
    int i = blockIdx.x * blockDim.x + threadIdx.x;
    if (i >= kEdges) return;
    int s, d;
    if (g_is64) {
        const long long* p = (const long long*)idx;
        s = (int)p[i]; d = (int)p[kEdges + i];
    } else {
        const int* p = (const int*)idx;
        s = p[i]; d = p[kEdges + i];
    }
    g_src[i] = s; g_dst[i] = d;
}
// Activation prep: round to tf32 AND apply per-8-group k interleave.
__global__ void perm_round_kernel(const float* __restrict__ src, float* __restrict__ dst,
                                  int total, int C) {
    int i = blockIdx.x * blockDim.x + threadIdx.x;
    if (i >= total) return;
    int row = i / C, k = i - row * C;
    int pos = (k & ~7) + 2 * (k & 3) + ((k & 4) >> 2);
    dst[(size_t)row * C + pos] = tf32_rn(src[i]);
}
// Weight prep: W[k][n] (KxN) -> Bt[n][pos(k)], rounded.
__global__ void trans_round_kernel(const float* __restrict__ W, float* __restrict__ Bt,
                                   int K, int N) {
    int i = blockIdx.x * blockDim.x + threadIdx.x;
    if (i >= K * N) return;
    int k = i / N, n = i - k * N;
    int pos = (k & ~7) + 2 * (k & 3) + ((k & 4) >> 2);
    Bt[(size_t)n * K + pos] = tf32_rn(W[(size_t)k * N + n]);
}
__global__ void init_out_kernel(float* __restrict__ out, const float* __restrict__ b3) {
    int i = blockIdx.x * blockDim.x + threadIdx.x;
    if (i < kEdges) out[i] = b3[0];
}

// ============================================================================
// TF32 mma.sync GEMM.  C[M,N] = relu(A[M,K] @ Bt[N,K]^T + bias)
//   EPI=0 : store C rounded+k-permuted (feeds next GEMM as A)
//   EPI=1 : fused dot with W3: atomicAdd into out[m] (pre-init to b3)
//   GATHER: A row e = concat(node_f[src[e]], node_f[dst[e]], edge_f[e])
// CTA 128x128, BK=32, 8 warps (2Mx4N), warp tile 64x32, 3-stage cp.async ring.
// A smem: row*32 floats, 16B chunk j swizzled j^(row&7); A gmem is k-permuted
// so each thread's (k, k+4) fragment pair is one LDS.64.
// ============================================================================
template <int K, int N, int EPI, bool GATHER>
__global__ __launch_bounds__(256, 2)
void mm_kernel(const float* __restrict__ A, const float* __restrict__ Bt,
               const float* __restrict__ bias, float* __restrict__ Cmat,
               const float* __restrict__ W3, float* __restrict__ outv, int M)
{
    constexpr int NS = K / 32;
    extern __shared__ float smf[];
    float* sAf   = smf;             // 3 x 4096
    float* sBf   = smf + 12288;     // 3 x 4096
    float* sBias = smf + 24576;     // 128
    float* sW3   = smf + 24704;     // 128
    int*   sSrc  = (int*)(smf + 24832);
    int*   sDst  = (int*)(smf + 24960);

    const int tid  = threadIdx.x;
    const int lane = tid & 31;
    const int warp = tid >> 5;
    const int r    = lane >> 2;      // 0..7
    const int c    = lane & 3;       // 0..3
    const int wm   = (warp >> 2) * 64;
    const int wnl  = (warp & 3) * 32;
    const int bn   = blockIdx.x * 128;
    const int bm   = blockIdx.y * 128;

    if (tid < 128) sBias[tid] = __ldg(bias + bn + tid);
    if (EPI == 1 && tid < 128) sW3[tid] = __ldg(W3 + bn + tid);
    if (GATHER && tid < 128) {
        int e = min(bm + tid, M - 1);
        sSrc[tid] = g_src[e];
        sDst[tid] = g_dst[e];
    }
    __syncthreads();

    auto load_stage = [&](int s) {
        const int buf = s % 3;
        const int k0 = s * 32;
        float* dA = sAf + buf * 4096;
        float* dB = sBf + buf * 4096;
#pragma unroll
        for (int t = 0; t < 4; ++t) {
            int idx = tid + t * 256;
            int row = idx >> 3, j = idx & 7;
            float* dst = dA + row * 32 + ((j ^ (row & 7)) << 2);
            const float* src;
            if (GATHER) {
                int koff = (k0 & 127) + j * 4;
                if (k0 < 128)      src = g_node_f + (size_t)sSrc[row] * 128 + koff;
                else if (k0 < 256) src = g_node_f + (size_t)sDst[row] * 128 + koff;
                else               src = g_edge_f + (size_t)min(bm + row, M - 1) * 128 + koff;
            } else {
                src = A + (size_t)min(bm + row, M - 1) * K + k0 + j * 4;
            }
            cp_async16(dst, src);
        }
#pragma unroll
        for (int t = 0; t < 4; ++t) {
            int idx = tid + t * 256;
            int n = idx >> 3, c4 = idx & 7;
            float* dst = dB + (c4 >> 1) * 1024 + n * 8 + (c4 & 1) * 4;
            cp_async16(dst, Bt + (size_t)(bn + n) * K + k0 + c4 * 4);
        }
    };

    float cf[4][4][4] = {};

    load_stage(0); cp_commit();
    if (NS > 1) { load_stage(1); cp_commit(); }

    for (int s = 0; s < NS; ++s) {
        if (s + 1 < NS) cp_wait1(); else cp_wait0();
        __syncthreads();
        if (s + 2 < NS) { load_stage(s + 2); cp_commit(); }

        const float* fA = sAf + (s % 3) * 4096;
        const float* fB = sBf + (s % 3) * 4096;
#pragma unroll
        for (int k8 = 0; k8 < 4; ++k8) {
            const int joff = ((k8 * 2 + (c >> 1)) ^ r) * 4 + (c & 1) * 2;
            uint32_t av[4][4];
#pragma unroll
            for (int ma = 0; ma < 4; ++ma) {
                const int row0 = wm + ma * 16 + r;
                const float2 v0 = *(const float2*)(fA + row0 * 32 + joff);
                const float2 v1 = *(const float2*)(fA + (row0 + 8) * 32 + joff);
                av[ma][0] = __float_as_uint(v0.x);
                av[ma][2] = __float_as_uint(v0.y);
                av[ma][1] = __float_as_uint(v1.x);
                av[ma][3] = __float_as_uint(v1.y);
            }
            uint32_t bv[4][2];
#pragma unroll
            for (int na = 0; na < 4; ++na) {
                const float2 t2 = *(const float2*)(fB + k8 * 1024 + (wnl + na * 8 + r) * 8 + 2 * c);
                bv[na][0] = __float_as_uint(t2.x);
                bv[na][1] = __float_as_uint(t2.y);
            }
#pragma unroll
            for (int ma = 0; ma < 4; ++ma)
#pragma unroll
                for (int na = 0; na < 4; ++na)
                    mma1688(cf[ma][na], av[ma], bv[na]);
        }
    }
    __syncthreads();   // all compute done before any smem reuse below

    // ---- epilogue ----
    float2 bias2[4];
#pragma unroll
    for (int na = 0; na < 4; ++na)
        bias2[na] = *(const float2*)&sBias[wnl + na * 8 + 2 * c];

    if (EPI == 0) {
        // permuted positions of logical local cols 2c and 2c+1 within an 8-group
        const int p0 = (((2 * c) & 3) << 1) | ((c >> 1) & 1);
        const int p1 = (((2 * c + 1) & 3) << 1) | (((2 * c + 1) & 4) >> 2);
#pragma unroll
        for (int ma = 0; ma < 4; ++ma) {
            const int row0 = bm + wm + ma * 16 + r;
            const int row1 = row0 + 8;
#pragma unroll
            for (int na = 0; na < 4; ++na) {
                const int gb = bn + wnl + na * 8;
                if (row0 < M) {
                    Cmat[(size_t)row0 * N + gb + p0] = tf32_rn(fmaxf(cf[ma][na][0] + bias2[na].x, 0.f));
                    Cmat[(size_t)row0 * N + gb + p1] = tf32_rn(fmaxf(cf[ma][na][1] + bias2[na].y, 0.f));
                }
                if (row1 < M) {
                    Cmat[(size_t)row1 * N + gb + p0] = tf32_rn(fmaxf(cf[ma][na][2] + bias2[na].x, 0.f));
                    Cmat[(size_t)row1 * N + gb + p1] = tf32_rn(fmaxf(cf[ma][na][3] + bias2[na].y, 0.f));
                }
            }
        }
    } else {
        float2 w3v[4];
#pragma unroll
        for (int na = 0; na < 4; ++na)
            w3v[na] = *(const float2*)&sW3[wnl + na * 8 + 2 * c];
        float* psum = sAf;                    // smem dead after mainloop sync
#pragma unroll
        for (int ma = 0; ma < 4; ++ma) {
            float p0 = 0.f, p1 = 0.f;
#pragma unroll
            for (int na = 0; na < 4; ++na) {
                p0 += fmaxf(cf[ma][na][0] + bias2[na].x, 0.f) * w3v[na].x
                    + fmaxf(cf[ma][na][1] + bias2[na].y, 0.f) * w3v[na].y;
                p1 += fmaxf(cf[ma][na][2] + bias2[na].x, 0.f) * w3v[na].x
                    + fmaxf(cf[ma][na][3] + bias2[na].y, 0.f) * w3v[na].y;
            }
            p0 += __shfl_xor_sync(0xffffffffu, p0, 1);
            p0 += __shfl_xor_sync(0xffffffffu, p0, 2);
            p1 += __shfl_xor_sync(0xffffffffu, p1, 1);
            p1 += __shfl_xor_sync(0xffffffffu, p1, 2);
            if (c == 0) {
                const int rl = wm + ma * 16 + r;
                psum[rl * 4 + (warp & 3)] = p0;
                psum[(rl + 8) * 4 + (warp & 3)] = p1;
            }
        }
        __syncthreads();
        if (tid < 128) {
            const int gm = bm + tid;
            if (gm < M)
                atomicAdd(outv + gm,
                          psum[tid * 4] + psum[tid * 4 + 1] + psum[tid * 4 + 2] + psum[tid * 4 + 3]);
        }
    }
}

// ============================================================================
extern "C" void kernel_launch(void* const* d_in, const int* in_sizes, int n_in,
                              void* d_out, int out_size)
{
    const float* x     = (const float*)d_in[0];
    const void*  eidx  = d_in[1];
    const float* eattr = (const float*)d_in[2];
    const float* Wn    = (const float*)d_in[3];
    const float* bnode = (const float*)d_in[4];
    const float* We    = (const float*)d_in[5];
    const float* be    = (const float*)d_in[6];
    const float* W1    = (const float*)d_in[7];
    const float* b1    = (const float*)d_in[8];
    const float* W2    = (const float*)d_in[9];
    const float* b2    = (const float*)d_in[10];
    const float* W3    = (const float*)d_in[11];
    const float* b3    = (const float*)d_in[12];
    float* out = (float*)d_out;

    float *p_node, *p_edge, *p_h1, *p_xt, *p_eat, *p_wnt, *p_wet, *p_w1t, *p_w2t;
    cudaGetSymbolAddress((void**)&p_node, g_node_f);
    cudaGetSymbolAddress((void**)&p_edge, g_edge_f);
    cudaGetSymbolAddress((void**)&p_h1, g_h1);
    cudaGetSymbolAddress((void**)&p_xt, g_xt);
    cudaGetSymbolAddress((void**)&p_eat, g_eat);
    cudaGetSymbolAddress((void**)&p_wnt, g_wnt);
    cudaGetSymbolAddress((void**)&p_wet, g_wet);
    cudaGetSymbolAddress((void**)&p_w1t, g_w1t);
    cudaGetSymbolAddress((void**)&p_w2t, g_w2t);

    detect_idx_kernel<<<1, 32>>>(eidx);
    conv_idx_kernel<<<(kEdges + 255) / 256, 256>>>(eidx);
    init_out_kernel<<<(kEdges + 255) / 256, 256>>>(out, b3);

    perm_round_kernel<<<(kNodes * 128 + 255) / 256, 256>>>(x, p_xt, kNodes * 128, 128);
    perm_round_kernel<<<(kEdges * 64 + 255) / 256, 256>>>(eattr, p_eat, kEdges * 64, 64);
    trans_round_kernel<<<(128 * 128 + 255) / 256, 256>>>(Wn, p_wnt, 128, 128);
    trans_round_kernel<<<(64 * 128 + 255) / 256, 256>>>(We, p_wet, 64, 128);
    trans_round_kernel<<<(384 * 512 + 255) / 256, 256>>>(W1, p_w1t, 384, 512);
    trans_round_kernel<<<(512 * 256 + 255) / 256, 256>>>(W2, p_w2t, 512, 256);

    // node encoder [50000,128]
    cudaFuncSetAttribute(mm_kernel<128, 128, 0, false>,
                         cudaFuncAttributeMaxDynamicSharedMemorySize, SMEM_BYTES);
    mm_kernel<128, 128, 0, false><<<dim3(1, (kNodes + 127) / 128), 256, SMEM_BYTES>>>(
        p_xt, p_wnt, bnode, p_node, nullptr, nullptr, kNodes);

    // edge encoder [500000,128]
    cudaFuncSetAttribute(mm_kernel<64, 128, 0, false>,
                         cudaFuncAttributeMaxDynamicSharedMemorySize, SMEM_BYTES);
    mm_kernel<64, 128, 0, false><<<dim3(1, (kEdges + 127) / 128), 256, SMEM_BYTES>>>(
        p_eat, p_wet, be, p_edge, nullptr, nullptr, kEdges);

    // W1 gather-fused: [500000,512]
    cudaFuncSetAttribute(mm_kernel<384, 512, 0, true>,
                         cudaFuncAttributeMaxDynamicSharedMemorySize, SMEM_BYTES);
    mm_kernel<384, 512, 0, true><<<dim3(4, (kEdges + 127) / 128), 256, SMEM_BYTES>>>(
        nullptr, p_w1t, b1, p_h1, nullptr, nullptr, kEdges);

    // W2 + fused final dot
    cudaFuncSetAttribute(mm_kernel<512, 256, 1, false>,
                         cudaFuncAttributeMaxDynamicSharedMemorySize, SMEM_BYTES);
    mm_kernel<512, 256, 1, false><<<dim3(2, (kEdges + 127) / 128), 256, SMEM_BYTES>>>(
        p_h1, p_w2t, b2, nullptr, W3, out, kEdges);
}

// round 7
// speedup vs baseline: 6.9786x; 2.1714x over previous
#include <cuda_runtime.h>
#include <cuda_fp16.h>
#include <cstdint>

namespace {
constexpr int kNodes = 50000;
constexpr int kEdges = 500000;
// bytes: sA 3*8192 | sB 3*8192 | bias 512 | w3 512 | src 512 | dst 512
constexpr int SMEM_BYTES = 24576 * 2 + 2048;   // 51200
}

// ============================================================================
// Static device scratch. All half matrices are stored K-PERMUTED per 16-group:
//   pos(k) = (k&~15) + ((k&7)>>1)*4 + (k&1) + ((k>>3)&1)*2
// so a thread's m16n8k16 fragment (k = 2c,2c+1,2c+8,2c+9) is 8 contiguous bytes.
// ============================================================================
__device__ __half g_node_f[(size_t)kNodes * 128];
__device__ __half g_edge_f[(size_t)kEdges * 128];
__device__ __half g_h1[(size_t)kEdges * 512];
__device__ __half g_xt[(size_t)kNodes * 128];
__device__ __half g_eat[(size_t)kEdges * 64];
__device__ __half g_wnt[128 * 128];
__device__ __half g_wet[128 * 64];
__device__ __half g_w1t[512 * 384];
__device__ __half g_w2t[256 * 512];
__device__ int    g_src[kEdges];
__device__ int    g_dst[kEdges];
__device__ int    g_is64;

// ============================================================================
// Helpers
// ============================================================================
__device__ __forceinline__ void cp_async16(void* smem, const void* gmem) {
    uint32_t s;
    asm("{ .reg .u64 t; cvta.to.shared.u64 t, %1; cvt.u32.u64 %0, t; }" : "=r"(s) : "l"(smem));
    asm volatile("cp.async.cg.shared.global [%0], [%1], 16;\n" :: "r"(s), "l"(gmem));
}
__device__ __forceinline__ void cp_commit() { asm volatile("cp.async.commit_group;\n"); }
__device__ __forceinline__ void cp_wait0()  { asm volatile("cp.async.wait_group 0;\n" ::: "memory"); }
__device__ __forceinline__ void cp_wait1()  { asm volatile("cp.async.wait_group 1;\n" ::: "memory"); }

// mma m16n8k16 fp16 inputs, fp32 accumulate
__device__ __forceinline__ void mma16816(float* cc, uint32_t a0, uint32_t a1,
                                         uint32_t a2, uint32_t a3,
                                         uint32_t b0, uint32_t b1) {
    asm volatile(
        "mma.sync.aligned.m16n8k16.row.col.f32.f16.f16.f32 "
        "{%0,%1,%2,%3}, {%4,%5,%6,%7}, {%8,%9}, {%0,%1,%2,%3};"
        : "+f"(cc[0]), "+f"(cc[1]), "+f"(cc[2]), "+f"(cc[3])
        : "r"(a0), "r"(a1), "r"(a2), "r"(a3), "r"(b0), "r"(b1));
}

__host__ __device__ __forceinline__ int kperm(int k) {
    return (k & ~15) + (((k & 7) >> 1) << 2) + (k & 1) + (((k >> 3) & 1) << 1);
}

// ============================================================================
// Prep kernels
// ============================================================================
__global__ void detect_idx_kernel(const void* idx) {
    if (threadIdx.x == 0 && blockIdx.x == 0) {
        const long long* p = (const long long*)idx;
        int ok = 1;
        for (int i = 0; i < 256; ++i) {
            long long v = p[i];
            if (v < 0 || v >= kNodes) { ok = 0; break; }
        }
        g_is64 = ok;
    }
}
__global__ void conv_idx_kernel(const void* idx) {
    int i = blockIdx.x * blockDim.x + threadIdx.x;
    if (i >= kEdges) return;
    int s, d;
    if (g_is64) {
        const long long* p = (const long long*)idx;
        s = (int)p[i]; d = (int)p[kEdges + i];
    } else {
        const int* p = (const int*)idx;
        s = p[i]; d = p[kEdges + i];
    }
    g_src[i] = s; g_dst[i] = d;
}
// fp32 -> fp16 (RN) with k interleave (activations, C cols per row)
__global__ void perm_round_kernel(const float* __restrict__ src, __half* __restrict__ dst,
                                  int total, int C) {
    int i = blockIdx.x * blockDim.x + threadIdx.x;
    if (i >= total) return;
    int row = i / C, k = i - row * C;
    dst[(size_t)row * C + kperm(k)] = __float2half_rn(src[i]);
}
// W[k][n] (KxN) -> Bt[n][kperm(k)], fp16
__global__ void trans_round_kernel(const float* __restrict__ W, __half* __restrict__ Bt,
                                   int K, int N) {
    int i = blockIdx.x * blockDim.x + threadIdx.x;
    if (i >= K * N) return;
    int k = i / N, n = i - k * N;
    Bt[(size_t)n * K + kperm(k)] = __float2half_rn(W[(size_t)k * N + n]);
}
__global__ void init_out_kernel(float* __restrict__ out, const float* __restrict__ b3) {
    int i = blockIdx.x * blockDim.x + threadIdx.x;
    if (i < kEdges) out[i] = b3[0];
}

// ============================================================================
// FP16 mma.sync GEMM.  C[M,N] = relu(A[M,K] @ Bt[N,K]^T + bias)
//   EPI=0 : store C as fp16, k-permuted (feeds next GEMM as A)
//   EPI=1 : fused dot with W3 (fp32): atomicAdd into out[m] (pre-init b3)
//   GATHER: A row e = concat(node_f[src[e]], node_f[dst[e]], edge_f[e])
// CTA 128x128, BK=32 halves, 8 warps (2Mx4N), warp tile 64x32, 3-stage ring.
// smem tiles: 128 rows x 64B, 16B chunk j stored at j^(row&3).
// ============================================================================
template <int K, int N, int EPI, bool GATHER>
__global__ __launch_bounds__(256, 2)
void mm_kernel(const __half* __restrict__ A, const __half* __restrict__ Bt,
               const float* __restrict__ bias, __half* __restrict__ Cmat,
               const float* __restrict__ W3, float* __restrict__ outv, int M)
{
    constexpr int NS = K / 32;
    extern __shared__ char smc[];
    char*  sAc   = smc;                       // 3 x 8192
    char*  sBc   = smc + 24576;               // 3 x 8192
    float* sBias = (float*)(smc + 49152);     // 128 f32
    float* sW3   = (float*)(smc + 49664);     // 128 f32
    int*   sSrc  = (int*)(smc + 50176);
    int*   sDst  = (int*)(smc + 50688);

    const int tid  = threadIdx.x;
    const int lane = tid & 31;
    const int warp = tid >> 5;
    const int r    = lane >> 2;      // 0..7
    const int c    = lane & 3;       // 0..3
    const int wm   = (warp >> 2) * 64;
    const int wnl  = (warp & 3) * 32;
    const int bn   = blockIdx.x * 128;
    const int bm   = blockIdx.y * 128;

    if (tid < 128) sBias[tid] = __ldg(bias + bn + tid);
    if (EPI == 1 && tid < 128) sW3[tid] = __ldg(W3 + bn + tid);
    if (GATHER && tid < 128) {
        int e = min(bm + tid, M - 1);
        sSrc[tid] = g_src[e];
        sDst[tid] = g_dst[e];
    }
    __syncthreads();

    auto load_stage = [&](int s) {
        const int buf = s % 3;
        const int k0 = s * 32;
        char* dA = sAc + buf * 8192;
        char* dB = sBc + buf * 8192;
#pragma unroll
        for (int t = 0; t < 2; ++t) {
            int idx = tid + t * 256;           // 0..511
            int row = idx >> 2, j = idx & 3;   // 4 chunks of 16B per 64B row
            char* dst = dA + row * 64 + ((j ^ (row & 3)) << 4);
            const __half* src;
            if (GATHER) {
                int koff = (k0 & 127) + j * 8;
                if (k0 < 128)      src = g_node_f + (size_t)sSrc[row] * 128 + koff;
                else if (k0 < 256) src = g_node_f + (size_t)sDst[row] * 128 + koff;
                else               src = g_edge_f + (size_t)min(bm + row, M - 1) * 128 + koff;
            } else {
                src = A + (size_t)min(bm + row, M - 1) * K + k0 + j * 8;
            }
            cp_async16(dst, src);
        }
#pragma unroll
        for (int t = 0; t < 2; ++t) {
            int idx = tid + t * 256;
            int n = idx >> 2, j = idx & 3;
            char* dst = dB + n * 64 + ((j ^ (n & 3)) << 4);
            cp_async16(dst, Bt + (size_t)(bn + n) * K + k0 + j * 8);
        }
    };

    float cf[4][4][4] = {};

    load_stage(0); cp_commit();
    if (NS > 1) { load_stage(1); cp_commit(); }

    for (int s = 0; s < NS; ++s) {
        if (s + 1 < NS) cp_wait1(); else cp_wait0();
        __syncthreads();
        if (s + 2 < NS) { load_stage(s + 2); cp_commit(); }

        const char* fA = sAc + (s % 3) * 8192;
        const char* fB = sBc + (s % 3) * 8192;
#pragma unroll
        for (int g = 0; g < 2; ++g) {           // two k16 steps per stage
            const int coff = (((g * 2 + (c >> 1)) ^ (r & 3)) << 4) + (c & 1) * 8;
            uint2 ua[4], ub_[4], ubv[4];
#pragma unroll
            for (int ma = 0; ma < 4; ++ma) {
                const int row0 = wm + ma * 16 + r;
                ua[ma]  = *(const uint2*)(fA + row0 * 64 + coff);        // a0,a2
                ub_[ma] = *(const uint2*)(fA + (row0 + 8) * 64 + coff);  // a1,a3
            }
#pragma unroll
            for (int na = 0; na < 4; ++na) {
                const int nrow = wnl + na * 8 + r;
                ubv[na] = *(const uint2*)(fB + nrow * 64 + coff);        // b0,b1
            }
#pragma unroll
            for (int ma = 0; ma < 4; ++ma)
#pragma unroll
                for (int na = 0; na < 4; ++na)
                    mma16816(cf[ma][na], ua[ma].x, ub_[ma].x, ua[ma].y, ub_[ma].y,
                             ubv[na].x, ubv[na].y);
        }
    }
    __syncthreads();   // compute done before smem reuse

    // ---- epilogue ----
    float2 bias2[4];
#pragma unroll
    for (int na = 0; na < 4; ++na)
        bias2[na] = *(const float2*)&sBias[wnl + na * 8 + 2 * c];

    if (EPI == 0) {
#pragma unroll
        for (int ma = 0; ma < 4; ++ma) {
            const int row0 = bm + wm + ma * 16 + r;
            const int row1 = row0 + 8;
#pragma unroll
            for (int na = 0; na < 4; ++na) {
                const int nloc = wnl + na * 8 + 2 * c;        // even
                const int pcol = bn + (nloc & ~15) + 4 * c + 2 * ((nloc >> 3) & 1);
                if (row0 < M) {
                    __half2 h;
                    h.x = __float2half_rn(fmaxf(cf[ma][na][0] + bias2[na].x, 0.f));
                    h.y = __float2half_rn(fmaxf(cf[ma][na][1] + bias2[na].y, 0.f));
                    *(__half2*)(Cmat + (size_t)row0 * N + pcol) = h;
                }
                if (row1 < M) {
                    __half2 h;
                    h.x = __float2half_rn(fmaxf(cf[ma][na][2] + bias2[na].x, 0.f));
                    h.y = __float2half_rn(fmaxf(cf[ma][na][3] + bias2[na].y, 0.f));
                    *(__half2*)(Cmat + (size_t)row1 * N + pcol) = h;
                }
            }
        }
    } else {
        float2 w3v[4];
#pragma unroll
        for (int na = 0; na < 4; ++na)
            w3v[na] = *(const float2*)&sW3[wnl + na * 8 + 2 * c];
        float* psum = (float*)smc;               // smem dead after mainloop sync
#pragma unroll
        for (int ma = 0; ma < 4; ++ma) {
            float p0 = 0.f, p1 = 0.f;
#pragma unroll
            for (int na = 0; na < 4; ++na) {
                p0 += fmaxf(cf[ma][na][0] + bias2[na].x, 0.f) * w3v[na].x
                    + fmaxf(cf[ma][na][1] + bias2[na].y, 0.f) * w3v[na].y;
                p1 += fmaxf(cf[ma][na][2] + bias2[na].x, 0.f) * w3v[na].x
                    + fmaxf(cf[ma][na][3] + bias2[na].y, 0.f) * w3v[na].y;
            }
            p0 += __shfl_xor_sync(0xffffffffu, p0, 1);
            p0 += __shfl_xor_sync(0xffffffffu, p0, 2);
            p1 += __shfl_xor_sync(0xffffffffu, p1, 1);
            p1 += __shfl_xor_sync(0xffffffffu, p1, 2);
            if (c == 0) {
                const int rl = wm + ma * 16 + r;
                psum[rl * 4 + (warp & 3)] = p0;
                psum[(rl + 8) * 4 + (warp & 3)] = p1;
            }
        }
        __syncthreads();
        if (tid < 128) {
            const int gm = bm + tid;
            if (gm < M)
                atomicAdd(outv + gm,
                          psum[tid * 4] + psum[tid * 4 + 1] + psum[tid * 4 + 2] + psum[tid * 4 + 3]);
        }
    }
}

// ============================================================================
extern "C" void kernel_launch(void* const* d_in, const int* in_sizes, int n_in,
                              void* d_out, int out_size)
{
    const float* x     = (const float*)d_in[0];
    const void*  eidx  = d_in[1];
    const float* eattr = (const float*)d_in[2];
    const float* Wn    = (const float*)d_in[3];
    const float* bnode = (const float*)d_in[4];
    const float* We    = (const float*)d_in[5];
    const float* be    = (const float*)d_in[6];
    const float* W1    = (const float*)d_in[7];
    const float* b1    = (const float*)d_in[8];
    const float* W2    = (const float*)d_in[9];
    const float* b2    = (const float*)d_in[10];
    const float* W3    = (const float*)d_in[11];
    const float* b3    = (const float*)d_in[12];
    float* out = (float*)d_out;

    __half *p_node, *p_edge, *p_h1, *p_xt, *p_eat, *p_wnt, *p_wet, *p_w1t, *p_w2t;
    cudaGetSymbolAddress((void**)&p_node, g_node_f);
    cudaGetSymbolAddress((void**)&p_edge, g_edge_f);
    cudaGetSymbolAddress((void**)&p_h1, g_h1);
    cudaGetSymbolAddress((void**)&p_xt, g_xt);
    cudaGetSymbolAddress((void**)&p_eat, g_eat);
    cudaGetSymbolAddress((void**)&p_wnt, g_wnt);
    cudaGetSymbolAddress((void**)&p_wet, g_wet);
    cudaGetSymbolAddress((void**)&p_w1t, g_w1t);
    cudaGetSymbolAddress((void**)&p_w2t, g_w2t);

    detect_idx_kernel<<<1, 32>>>(eidx);
    conv_idx_kernel<<<(kEdges + 255) / 256, 256>>>(eidx);
    init_out_kernel<<<(kEdges + 255) / 256, 256>>>(out, b3);

    perm_round_kernel<<<(kNodes * 128 + 255) / 256, 256>>>(x, p_xt, kNodes * 128, 128);
    perm_round_kernel<<<(kEdges * 64 + 255) / 256, 256>>>(eattr, p_eat, kEdges * 64, 64);
    trans_round_kernel<<<(128 * 128 + 255) / 256, 256>>>(Wn, p_wnt, 128, 128);
    trans_round_kernel<<<(64 * 128 + 255) / 256, 256>>>(We, p_wet, 64, 128);
    trans_round_kernel<<<(384 * 512 + 255) / 256, 256>>>(W1, p_w1t, 384, 512);
    trans_round_kernel<<<(512 * 256 + 255) / 256, 256>>>(W2, p_w2t, 512, 256);

    // node encoder [50000,128]
    cudaFuncSetAttribute(mm_kernel<128, 128, 0, false>,
                         cudaFuncAttributeMaxDynamicSharedMemorySize, SMEM_BYTES);
    mm_kernel<128, 128, 0, false><<<dim3(1, (kNodes + 127) / 128), 256, SMEM_BYTES>>>(
        p_xt, p_wnt, bnode, p_node, nullptr, nullptr, kNodes);

    // edge encoder [500000,128]
    cudaFuncSetAttribute(mm_kernel<64, 128, 0, false>,
                         cudaFuncAttributeMaxDynamicSharedMemorySize, SMEM_BYTES);
    mm_kernel<64, 128, 0, false><<<dim3(1, (kEdges + 127) / 128), 256, SMEM_BYTES>>>(
        p_eat, p_wet, be, p_edge, nullptr, nullptr, kEdges);

    // W1 gather-fused: [500000,512]
    cudaFuncSetAttribute(mm_kernel<384, 512, 0, true>,
                         cudaFuncAttributeMaxDynamicSharedMemorySize, SMEM_BYTES);
    mm_kernel<384, 512, 0, true><<<dim3(4, (kEdges + 127) / 128), 256, SMEM_BYTES>>>(
        nullptr, p_w1t, b1, p_h1, nullptr, nullptr, kEdges);

    // W2 + fused final dot
    cudaFuncSetAttribute(mm_kernel<512, 256, 1, false>,
                         cudaFuncAttributeMaxDynamicSharedMemorySize, SMEM_BYTES);
    mm_kernel<512, 256, 1, false><<<dim3(2, (kEdges + 127) / 128), 256, SMEM_BYTES>>>(
        p_h1, p_w2t, b2, nullptr, W3, out, kEdges);
}

// round 8
// speedup vs baseline: 8.6252x; 1.2359x over previous
#include <cuda_runtime.h>
#include <cuda_fp16.h>
#include <cstdint>

namespace {
constexpr int kNodes = 50000;
constexpr int kEdges = 500000;
constexpr int MM_SMEM = 50176;   // sA 3*8K | sB 3*8K | bias 512B
constexpr int W2_SMEM = 61440;   // sA 2*4K | sB 3*16K | b2 1K | w3 1K | src/dst 512B
}

// ============================================================================
// Static scratch. All half matrices K-PERMUTED per 16-group:
//   kperm(k) = (k&~15) + ((k&7)>>1)*4 + (k&1) + ((k>>3)&1)*2
// ============================================================================
__device__ __half g_node_f[(size_t)kNodes * 128];
__device__ __half g_edge_f[(size_t)kEdges * 128];
__device__ __half g_q[(size_t)kEdges * 512];      // edge_f @ W1c
__device__ __half g_pab[(size_t)kNodes * 1024];   // [node_f@W1a + b1 | node_f@W1b]
__device__ __half g_xt[(size_t)kNodes * 128];
__device__ __half g_eat[(size_t)kEdges * 64];
__device__ __half g_wnt[128 * 128];
__device__ __half g_wet[128 * 64];
__device__ __half g_w1ab[1024 * 128];
__device__ __half g_w1c[512 * 128];
__device__ __half g_w2t[256 * 512];
__device__ float  g_bias1024[1024];
__device__ int    g_src[kEdges];
__device__ int    g_dst[kEdges];
__device__ int    g_is64;

// ============================================================================
// Helpers
// ============================================================================
__device__ __forceinline__ void cp_async16(void* smem, const void* gmem) {
    uint32_t s;
    asm("{ .reg .u64 t; cvta.to.shared.u64 t, %1; cvt.u32.u64 %0, t; }" : "=r"(s) : "l"(smem));
    asm volatile("cp.async.cg.shared.global [%0], [%1], 16;\n" :: "r"(s), "l"(gmem));
}
__device__ __forceinline__ void cp_commit() { asm volatile("cp.async.commit_group;\n"); }
__device__ __forceinline__ void cp_wait0()  { asm volatile("cp.async.wait_group 0;\n" ::: "memory"); }
__device__ __forceinline__ void cp_wait1()  { asm volatile("cp.async.wait_group 1;\n" ::: "memory"); }

__device__ __forceinline__ void mma16816(float* cc, uint32_t a0, uint32_t a1,
                                         uint32_t a2, uint32_t a3,
                                         uint32_t b0, uint32_t b1) {
    asm volatile(
        "mma.sync.aligned.m16n8k16.row.col.f32.f16.f16.f32 "
        "{%0,%1,%2,%3}, {%4,%5,%6,%7}, {%8,%9}, {%0,%1,%2,%3};"
        : "+f"(cc[0]), "+f"(cc[1]), "+f"(cc[2]), "+f"(cc[3])
        : "r"(a0), "r"(a1), "r"(a2), "r"(a3), "r"(b0), "r"(b1));
}
__host__ __device__ __forceinline__ int kperm(int k) {
    return (k & ~15) + (((k & 7) >> 1) << 2) + (k & 1) + (((k >> 3) & 1) << 1);
}

// ============================================================================
// Prep kernels
// ============================================================================
__global__ void detect_idx_kernel(const void* idx) {
    if (threadIdx.x == 0 && blockIdx.x == 0) {
        const long long* p = (const long long*)idx;
        int ok = 1;
        for (int i = 0; i < 256; ++i) {
            long long v = p[i];
            if (v < 0 || v >= kNodes) { ok = 0; break; }
        }
        g_is64 = ok;
    }
}
__global__ void conv_idx_kernel(const void* idx) {
    int i = blockIdx.x * blockDim.x + threadIdx.x;
    if (i >= kEdges) return;
    int s, d;
    if (g_is64) {
        const long long* p = (const long long*)idx;
        s = (int)p[i]; d = (int)p[kEdges + i];
    } else {
        const int* p = (const int*)idx;
        s = p[i]; d = p[kEdges + i];
    }
    g_src[i] = s; g_dst[i] = d;
}
__global__ void perm_round_kernel(const float* __restrict__ src, __half* __restrict__ dst,
                                  int total, int C) {
    int i = blockIdx.x * blockDim.x + threadIdx.x;
    if (i >= total) return;
    int row = i / C, k = i - row * C;
    dst[(size_t)row * C + kperm(k)] = __float2half_rn(src[i]);
}
__global__ void trans_round_kernel(const float* __restrict__ W, __half* __restrict__ Bt,
                                   int K, int N) {
    int i = blockIdx.x * blockDim.x + threadIdx.x;
    if (i >= K * N) return;
    int k = i / N, n = i - k * N;
    Bt[(size_t)n * K + kperm(k)] = __float2half_rn(W[(size_t)k * N + n]);
}
// W1 [384x512]: rows 0-127 -> W1a, 128-255 -> W1b, 256-383 -> W1c.
__global__ void trans_w1ab_kernel(const float* __restrict__ W1, __half* __restrict__ Bt) {
    int i = blockIdx.x * blockDim.x + threadIdx.x;
    if (i >= 1024 * 128) return;
    int n = i >> 7, k = i & 127;
    int srcRow = (n < 512) ? k : (128 + k);
    int srcCol = (n < 512) ? n : (n - 512);
    Bt[(size_t)n * 128 + kperm(k)] = __float2half_rn(W1[(size_t)srcRow * 512 + srcCol]);
}
__global__ void trans_w1c_kernel(const float* __restrict__ W1, __half* __restrict__ Bt) {
    int i = blockIdx.x * blockDim.x + threadIdx.x;
    if (i >= 512 * 128) return;
    int n = i >> 7, k = i & 127;
    Bt[(size_t)n * 128 + kperm(k)] = __float2half_rn(W1[(size_t)(256 + k) * 512 + n]);
}
__global__ void bias1024_kernel(const float* __restrict__ b1, float* __restrict__ dst) {
    int i = blockIdx.x * blockDim.x + threadIdx.x;
    if (i < 1024) dst[i] = (i < 512) ? b1[i] : 0.f;
}

// ============================================================================
// FP16 mma GEMM: C[M,N] = act(A[M,K] @ Bt[N,K]^T + bias), fp16 kperm store.
// CTA 128x128, BK=32, 8 warps (2Mx4N), warp 64x32, 3-stage cp.async ring.
// ============================================================================
template <int K, int N, bool RELU>
__global__ __launch_bounds__(256, 2)
void mm_kernel(const __half* __restrict__ A, const __half* __restrict__ Bt,
               const float* __restrict__ bias, __half* __restrict__ Cmat, int M)
{
    constexpr int NS = K / 32;
    extern __shared__ char smc[];
    char*  sAc   = smc;                       // 3 x 8192
    char*  sBc   = smc + 24576;               // 3 x 8192
    float* sBias = (float*)(smc + 49152);     // 128 f32

    const int tid  = threadIdx.x;
    const int lane = tid & 31;
    const int warp = tid >> 5;
    const int r    = lane >> 2;
    const int c    = lane & 3;
    const int wm   = (warp >> 2) * 64;
    const int wnl  = (warp & 3) * 32;
    const int bn   = blockIdx.x * 128;
    const int bm   = blockIdx.y * 128;

    if (tid < 128) sBias[tid] = bias ? __ldg(bias + bn + tid) : 0.f;
    __syncthreads();

    auto load_stage = [&](int s) {
        const int buf = s % 3;
        const int k0 = s * 32;
        char* dA = sAc + buf * 8192;
        char* dB = sBc + buf * 8192;
#pragma unroll
        for (int t = 0; t < 2; ++t) {
            int idx = tid + t * 256;
            int row = idx >> 2, j = idx & 3;
            char* dst = dA + row * 64 + ((j ^ (row & 3)) << 4);
            cp_async16(dst, A + (size_t)min(bm + row, M - 1) * K + k0 + j * 8);
        }
#pragma unroll
        for (int t = 0; t < 2; ++t) {
            int idx = tid + t * 256;
            int n = idx >> 2, j = idx & 3;
            char* dst = dB + n * 64 + ((j ^ (n & 3)) << 4);
            cp_async16(dst, Bt + (size_t)(bn + n) * K + k0 + j * 8);
        }
    };

    float cf[4][4][4] = {};
    load_stage(0); cp_commit();
    if (NS > 1) { load_stage(1); cp_commit(); }

    for (int s = 0; s < NS; ++s) {
        if (s + 1 < NS) cp_wait1(); else cp_wait0();
        __syncthreads();
        if (s + 2 < NS) { load_stage(s + 2); cp_commit(); }

        const char* fA = sAc + (s % 3) * 8192;
        const char* fB = sBc + (s % 3) * 8192;
#pragma unroll
        for (int g = 0; g < 2; ++g) {
            const int coff = (((g * 2 + (c >> 1)) ^ (r & 3)) << 4) + (c & 1) * 8;
            uint2 ua[4], ub_[4], ubv[4];
#pragma unroll
            for (int ma = 0; ma < 4; ++ma) {
                const int row0 = wm + ma * 16 + r;
                ua[ma]  = *(const uint2*)(fA + row0 * 64 + coff);
                ub_[ma] = *(const uint2*)(fA + (row0 + 8) * 64 + coff);
            }
#pragma unroll
            for (int na = 0; na < 4; ++na)
                ubv[na] = *(const uint2*)(fB + (wnl + na * 8 + r) * 64 + coff);
#pragma unroll
            for (int ma = 0; ma < 4; ++ma)
#pragma unroll
                for (int na = 0; na < 4; ++na)
                    mma16816(cf[ma][na], ua[ma].x, ub_[ma].x, ua[ma].y, ub_[ma].y,
                             ubv[na].x, ubv[na].y);
        }
    }
    __syncthreads();

    float2 bias2[4];
#pragma unroll
    for (int na = 0; na < 4; ++na)
        bias2[na] = *(const float2*)&sBias[wnl + na * 8 + 2 * c];

#pragma unroll
    for (int ma = 0; ma < 4; ++ma) {
        const int row0 = bm + wm + ma * 16 + r;
        const int row1 = row0 + 8;
#pragma unroll
        for (int na = 0; na < 4; ++na) {
            const int nloc = wnl + na * 8 + 2 * c;
            const int pcol = bn + (nloc & ~15) + 4 * c + 2 * ((nloc >> 3) & 1);
            float v0 = cf[ma][na][0] + bias2[na].x;
            float v1 = cf[ma][na][1] + bias2[na].y;
            float v2 = cf[ma][na][2] + bias2[na].x;
            float v3 = cf[ma][na][3] + bias2[na].y;
            if (RELU) {
                v0 = fmaxf(v0, 0.f); v1 = fmaxf(v1, 0.f);
                v2 = fmaxf(v2, 0.f); v3 = fmaxf(v3, 0.f);
            }
            if (row0 < M) {
                __half2 h; h.x = __float2half_rn(v0); h.y = __float2half_rn(v1);
                *(__half2*)(Cmat + (size_t)row0 * N + pcol) = h;
            }
            if (row1 < M) {
                __half2 h; h.x = __float2half_rn(v2); h.y = __float2half_rn(v3);
                *(__half2*)(Cmat + (size_t)row1 * N + pcol) = h;
            }
        }
    }
}

// ============================================================================
// Fused W2+W3: out[e] = relu( relu(Pa[src]+Pb[dst]+Q[e]) @ W2t^T + b2 ) . W3 + b3
// CTA: 64 rows x full N=256, K=512. A built on the fly (reg pipeline, LDG+STS),
// B (W2t) via 3-stage cp.async. 8 warps, each warp tile 64x32.
// ============================================================================
__global__ __launch_bounds__(256, 2)
void w2_kernel(const float* __restrict__ b2, const float* __restrict__ W3,
               const float* __restrict__ b3, float* __restrict__ outv, int M)
{
    constexpr int K = 512, NS = K / 32;
    extern __shared__ char smc[];
    char*  sAc  = smc;                        // 2 x 4096
    char*  sBc  = smc + 8192;                 // 3 x 16384
    float* sB2  = (float*)(smc + 57344);      // 256 f32
    float* sW3  = (float*)(smc + 58368);      // 256 f32
    int*   sSrc = (int*)(smc + 59392);        // 64
    int*   sDst = (int*)(smc + 59648);        // 64

    const int tid  = threadIdx.x;
    const int lane = tid & 31;
    const int warp = tid >> 5;
    const int r    = lane >> 2;
    const int c    = lane & 3;
    const int wnl  = warp * 32;
    const int bm   = blockIdx.x * 64;

    sB2[tid] = __ldg(b2 + tid);
    sW3[tid] = __ldg(W3 + tid);
    if (tid < 64) {
        int e = min(bm + tid, M - 1);
        sSrc[tid] = g_src[e];
        sDst[tid] = g_dst[e];
    }
    __syncthreads();

    const int arow = tid >> 2, aj = tid & 3;
    const size_t eRow = (size_t)min(bm + arow, M - 1);
    const __half* paP = g_pab + (size_t)sSrc[arow] * 1024;
    const __half* pbP = g_pab + (size_t)sDst[arow] * 1024 + 512;
    const __half* qP  = g_q + eRow * 512;

    uint4 ra, rb, rq;
    auto ldgA = [&](int s) {
        const int ko = s * 32 + aj * 8;
        ra = *(const uint4*)(paP + ko);
        rb = *(const uint4*)(pbP + ko);
        rq = *(const uint4*)(qP + ko);
    };
    auto stsA = [&](int s) {
        char* dA = sAc + (s & 1) * 4096;
        const half2* ha = (const half2*)&ra;
        const half2* hb = (const half2*)&rb;
        const half2* hq = (const half2*)&rq;
        half2 v[4];
        const half2 z = __float2half2_rn(0.f);
#pragma unroll
        for (int i = 0; i < 4; ++i)
            v[i] = __hmax2(__hadd2(__hadd2(ha[i], hb[i]), hq[i]), z);
        *(uint4*)(dA + arow * 64 + ((aj ^ (arow & 3)) << 4)) = *(uint4*)v;
    };
    auto cpB = [&](int s) {
        char* dB = sBc + (s % 3) * 16384;
        const int k0 = s * 32;
#pragma unroll
        for (int t = 0; t < 4; ++t) {
            int idx = tid + t * 256;
            int n = idx >> 2, j = idx & 3;
            cp_async16(dB + n * 64 + ((j ^ (n & 3)) << 4),
                       g_w2t + (size_t)n * 512 + k0 + j * 8);
        }
    };

    float cf[4][4][4] = {};

    ldgA(0);
    cpB(0); cp_commit();
    cpB(1); cp_commit();

    for (int s = 0; s < NS; ++s) {
        stsA(s);
        if (s + 1 < NS) ldgA(s + 1);
        if (s + 1 < NS) cp_wait1(); else cp_wait0();
        __syncthreads();
        if (s + 2 < NS) { cpB(s + 2); cp_commit(); }

        const char* fA = sAc + (s & 1) * 4096;
        const char* fB = sBc + (s % 3) * 16384;
#pragma unroll
        for (int g = 0; g < 2; ++g) {
            const int coff = (((g * 2 + (c >> 1)) ^ (r & 3)) << 4) + (c & 1) * 8;
            uint2 ua[4], ub_[4], ubv[4];
#pragma unroll
            for (int ma = 0; ma < 4; ++ma) {
                const int row0 = ma * 16 + r;
                ua[ma]  = *(const uint2*)(fA + row0 * 64 + coff);
                ub_[ma] = *(const uint2*)(fA + (row0 + 8) * 64 + coff);
            }
#pragma unroll
            for (int na = 0; na < 4; ++na)
                ubv[na] = *(const uint2*)(fB + (wnl + na * 8 + r) * 64 + coff);
#pragma unroll
            for (int ma = 0; ma < 4; ++ma)
#pragma unroll
                for (int na = 0; na < 4; ++na)
                    mma16816(cf[ma][na], ua[ma].x, ub_[ma].x, ua[ma].y, ub_[ma].y,
                             ubv[na].x, ubv[na].y);
        }
        __syncthreads();
    }

    // epilogue: relu(+b2), dot with W3, reduce
    float2 bias2[4], w3v[4];
#pragma unroll
    for (int na = 0; na < 4; ++na) {
        bias2[na] = *(const float2*)&sB2[wnl + na * 8 + 2 * c];
        w3v[na]   = *(const float2*)&sW3[wnl + na * 8 + 2 * c];
    }
    float* psum = (float*)sAc;   // 64 x 8 floats, smem dead
#pragma unroll
    for (int ma = 0; ma < 4; ++ma) {
        float p0 = 0.f, p1 = 0.f;
#pragma unroll
        for (int na = 0; na < 4; ++na) {
            p0 += fmaxf(cf[ma][na][0] + bias2[na].x, 0.f) * w3v[na].x
                + fmaxf(cf[ma][na][1] + bias2[na].y, 0.f) * w3v[na].y;
            p1 += fmaxf(cf[ma][na][2] + bias2[na].x, 0.f) * w3v[na].x
                + fmaxf(cf[ma][na][3] + bias2[na].y, 0.f) * w3v[na].y;
        }
        p0 += __shfl_xor_sync(0xffffffffu, p0, 1);
        p0 += __shfl_xor_sync(0xffffffffu, p0, 2);
        p1 += __shfl_xor_sync(0xffffffffu, p1, 1);
        p1 += __shfl_xor_sync(0xffffffffu, p1, 2);
        if (c == 0) {
            const int rl = ma * 16 + r;
            psum[rl * 8 + warp] = p0;
            psum[(rl + 8) * 8 + warp] = p1;
        }
    }
    __syncthreads();
    if (tid < 64) {
        const int gm = bm + tid;
        if (gm < M) {
            float s = 0.f;
#pragma unroll
            for (int w = 0; w < 8; ++w) s += psum[tid * 8 + w];
            outv[gm] = s + __ldg(b3);
        }
    }
}

// ============================================================================
extern "C" void kernel_launch(void* const* d_in, const int* in_sizes, int n_in,
                              void* d_out, int out_size)
{
    const float* x     = (const float*)d_in[0];
    const void*  eidx  = d_in[1];
    const float* eattr = (const float*)d_in[2];
    const float* Wn    = (const float*)d_in[3];
    const float* bnode = (const float*)d_in[4];
    const float* We    = (const float*)d_in[5];
    const float* be    = (const float*)d_in[6];
    const float* W1    = (const float*)d_in[7];
    const float* b1    = (const float*)d_in[8];
    const float* W2    = (const float*)d_in[9];
    const float* b2    = (const float*)d_in[10];
    const float* W3    = (const float*)d_in[11];
    const float* b3    = (const float*)d_in[12];
    float* out = (float*)d_out;

    __half *p_node, *p_edge, *p_q, *p_pab, *p_xt, *p_eat, *p_wnt, *p_wet, *p_w1ab, *p_w1c, *p_w2t;
    float* p_b1024;
    cudaGetSymbolAddress((void**)&p_node, g_node_f);
    cudaGetSymbolAddress((void**)&p_edge, g_edge_f);
    cudaGetSymbolAddress((void**)&p_q, g_q);
    cudaGetSymbolAddress((void**)&p_pab, g_pab);
    cudaGetSymbolAddress((void**)&p_xt, g_xt);
    cudaGetSymbolAddress((void**)&p_eat, g_eat);
    cudaGetSymbolAddress((void**)&p_wnt, g_wnt);
    cudaGetSymbolAddress((void**)&p_wet, g_wet);
    cudaGetSymbolAddress((void**)&p_w1ab, g_w1ab);
    cudaGetSymbolAddress((void**)&p_w1c, g_w1c);
    cudaGetSymbolAddress((void**)&p_w2t, g_w2t);
    cudaGetSymbolAddress((void**)&p_b1024, g_bias1024);

    detect_idx_kernel<<<1, 32>>>(eidx);
    conv_idx_kernel<<<(kEdges + 255) / 256, 256>>>(eidx);

    perm_round_kernel<<<(kNodes * 128 + 255) / 256, 256>>>(x, p_xt, kNodes * 128, 128);
    perm_round_kernel<<<(kEdges * 64 + 255) / 256, 256>>>(eattr, p_eat, kEdges * 64, 64);
    trans_round_kernel<<<(128 * 128 + 255) / 256, 256>>>(Wn, p_wnt, 128, 128);
    trans_round_kernel<<<(64 * 128 + 255) / 256, 256>>>(We, p_wet, 64, 128);
    trans_round_kernel<<<(512 * 256 + 255) / 256, 256>>>(W2, p_w2t, 512, 256);
    trans_w1ab_kernel<<<(1024 * 128 + 255) / 256, 256>>>(W1, p_w1ab);
    trans_w1c_kernel<<<(512 * 128 + 255) / 256, 256>>>(W1, p_w1c);
    bias1024_kernel<<<4, 256>>>(b1, p_b1024);

    // node encoder [50000,128]
    cudaFuncSetAttribute(mm_kernel<128, 128, true>,
                         cudaFuncAttributeMaxDynamicSharedMemorySize, MM_SMEM);
    mm_kernel<128, 128, true><<<dim3(1, (kNodes + 127) / 128), 256, MM_SMEM>>>(
        p_xt, p_wnt, bnode, p_node, kNodes);

    // edge encoder [500000,128]
    cudaFuncSetAttribute(mm_kernel<64, 128, true>,
                         cudaFuncAttributeMaxDynamicSharedMemorySize, MM_SMEM);
    mm_kernel<64, 128, true><<<dim3(1, (kEdges + 127) / 128), 256, MM_SMEM>>>(
        p_eat, p_wet, be, p_edge, kEdges);

    // Pab = node_f @ [W1a|W1b] + [b1|0]   [50000,1024], no relu
    cudaFuncSetAttribute(mm_kernel<128, 1024, false>,
                         cudaFuncAttributeMaxDynamicSharedMemorySize, MM_SMEM);
    mm_kernel<128, 1024, false><<<dim3(8, (kNodes + 127) / 128), 256, MM_SMEM>>>(
        p_node, p_w1ab, p_b1024, p_pab, kNodes);

    // Q = edge_f @ W1c   [500000,512], no bias/relu
    cudaFuncSetAttribute(mm_kernel<128, 512, false>,
                         cudaFuncAttributeMaxDynamicSharedMemorySize, MM_SMEM);
    mm_kernel<128, 512, false><<<dim3(4, (kEdges + 127) / 128), 256, MM_SMEM>>>(
        p_edge, p_w1c, nullptr, p_q, kEdges);

    // fused: out = relu(relu(Pa[src]+Pb[dst]+Q) @ W2 + b2) @ W3 + b3
    cudaFuncSetAttribute(w2_kernel,
                         cudaFuncAttributeMaxDynamicSharedMemorySize, W2_SMEM);
    w2_kernel<<<(kEdges + 63) / 64, 256, W2_SMEM>>>(b2, W3, b3, out, kEdges);
}

// round 9
// speedup vs baseline: 10.5329x; 1.2212x over previous
#include <cuda_runtime.h>
#include <cuda_fp16.h>
#include <cstdint>

namespace {
constexpr int kNodes = 50000;
constexpr int kEdges = 500000;
constexpr int MM_SMEM = 50176;    // mm_kernel: sA 3*8K | sB 3*8K | bias 512B
// fq_kernel: sQ 16*4K=64K | sEf 4*4K=16K | stream 2*16K=32K  => 114688
constexpr int FQ_SMEM = 114688;
}

// ============================================================================
// Static scratch. All half matrices K-PERMUTED per 16-group:
//   kperm(k) = (k&~15) + ((k&7)>>1)*4 + (k&1) + ((k>>3)&1)*2
// ============================================================================
__device__ __half g_node_f[(size_t)kNodes * 128];
__device__ __half g_pab[(size_t)kNodes * 1024];   // [node_f@W1a + b1 | node_f@W1b]
__device__ __half g_xt[(size_t)kNodes * 128];
__device__ __half g_wnt[128 * 128];
__device__ __half g_wet[128 * 64];
__device__ __half g_w1ab[1024 * 128];
__device__ __half g_w1c[512 * 128];
__device__ __half g_w2t[256 * 512];
__device__ float  g_bias1024[1024];
__device__ int    g_src[kEdges];
__device__ int    g_dst[kEdges];
__device__ int    g_is64;

// ============================================================================
// Helpers
// ============================================================================
__device__ __forceinline__ void cp_async16(void* smem, const void* gmem) {
    uint32_t s;
    asm("{ .reg .u64 t; cvta.to.shared.u64 t, %1; cvt.u32.u64 %0, t; }" : "=r"(s) : "l"(smem));
    asm volatile("cp.async.cg.shared.global [%0], [%1], 16;\n" :: "r"(s), "l"(gmem));
}
__device__ __forceinline__ void cp_commit() { asm volatile("cp.async.commit_group;\n"); }
__device__ __forceinline__ void cp_wait0()  { asm volatile("cp.async.wait_group 0;\n" ::: "memory"); }
__device__ __forceinline__ void cp_wait1()  { asm volatile("cp.async.wait_group 1;\n" ::: "memory"); }

__device__ __forceinline__ void mma16816(float* cc, uint32_t a0, uint32_t a1,
                                         uint32_t a2, uint32_t a3,
                                         uint32_t b0, uint32_t b1) {
    asm volatile(
        "mma.sync.aligned.m16n8k16.row.col.f32.f16.f16.f32 "
        "{%0,%1,%2,%3}, {%4,%5,%6,%7}, {%8,%9}, {%0,%1,%2,%3};"
        : "+f"(cc[0]), "+f"(cc[1]), "+f"(cc[2]), "+f"(cc[3])
        : "r"(a0), "r"(a1), "r"(a2), "r"(a3), "r"(b0), "r"(b1));
}
__host__ __device__ __forceinline__ int kperm(int k) {
    return (k & ~15) + (((k & 7) >> 1) << 2) + (k & 1) + (((k >> 3) & 1) << 1);
}

// ============================================================================
// Prep kernels
// ============================================================================
__global__ void detect_idx_kernel(const void* idx) {
    if (threadIdx.x == 0 && blockIdx.x == 0) {
        const long long* p = (const long long*)idx;
        int ok = 1;
        for (int i = 0; i < 256; ++i) {
            long long v = p[i];
            if (v < 0 || v >= kNodes) { ok = 0; break; }
        }
        g_is64 = ok;
    }
}
__global__ void conv_idx_kernel(const void* idx) {
    int i = blockIdx.x * blockDim.x + threadIdx.x;
    if (i >= kEdges) return;
    int s, d;
    if (g_is64) {
        const long long* p = (const long long*)idx;
        s = (int)p[i]; d = (int)p[kEdges + i];
    } else {
        const int* p = (const int*)idx;
        s = p[i]; d = p[kEdges + i];
    }
    g_src[i] = s; g_dst[i] = d;
}
__global__ void perm_round_kernel(const float* __restrict__ src, __half* __restrict__ dst,
                                  int total, int C) {
    int i = blockIdx.x * blockDim.x + threadIdx.x;
    if (i >= total) return;
    int row = i / C, k = i - row * C;
    dst[(size_t)row * C + kperm(k)] = __float2half_rn(src[i]);
}
__global__ void trans_round_kernel(const float* __restrict__ W, __half* __restrict__ Bt,
                                   int K, int N) {
    int i = blockIdx.x * blockDim.x + threadIdx.x;
    if (i >= K * N) return;
    int k = i / N, n = i - k * N;
    Bt[(size_t)n * K + kperm(k)] = __float2half_rn(W[(size_t)k * N + n]);
}
// W1 [384x512]: rows 0-127 -> W1a, 128-255 -> W1b, 256-383 -> W1c.
__global__ void trans_w1ab_kernel(const float* __restrict__ W1, __half* __restrict__ Bt) {
    int i = blockIdx.x * blockDim.x + threadIdx.x;
    if (i >= 1024 * 128) return;
    int n = i >> 7, k = i & 127;
    int srcRow = (n < 512) ? k : (128 + k);
    int srcCol = (n < 512) ? n : (n - 512);
    Bt[(size_t)n * 128 + kperm(k)] = __float2half_rn(W1[(size_t)srcRow * 512 + srcCol]);
}
__global__ void trans_w1c_kernel(const float* __restrict__ W1, __half* __restrict__ Bt) {
    int i = blockIdx.x * blockDim.x + threadIdx.x;
    if (i >= 512 * 128) return;
    int n = i >> 7, k = i & 127;
    Bt[(size_t)n * 128 + kperm(k)] = __float2half_rn(W1[(size_t)(256 + k) * 512 + n]);
}
__global__ void bias1024_kernel(const float* __restrict__ b1, float* __restrict__ dst) {
    int i = blockIdx.x * blockDim.x + threadIdx.x;
    if (i < 1024) dst[i] = (i < 512) ? b1[i] : 0.f;
}

// ============================================================================
// FP16 mma GEMM (node-side): C[M,N] = act(A@Bt^T + bias), fp16 kperm store.
// ============================================================================
template <int K, int N, bool RELU>
__global__ __launch_bounds__(256, 2)
void mm_kernel(const __half* __restrict__ A, const __half* __restrict__ Bt,
               const float* __restrict__ bias, __half* __restrict__ Cmat, int M)
{
    constexpr int NS = K / 32;
    extern __shared__ char smc[];
    char*  sAc   = smc;
    char*  sBc   = smc + 24576;
    float* sBias = (float*)(smc + 49152);

    const int tid  = threadIdx.x;
    const int lane = tid & 31;
    const int warp = tid >> 5;
    const int r    = lane >> 2;
    const int c    = lane & 3;
    const int wm   = (warp >> 2) * 64;
    const int wnl  = (warp & 3) * 32;
    const int bn   = blockIdx.x * 128;
    const int bm   = blockIdx.y * 128;

    if (tid < 128) sBias[tid] = bias ? __ldg(bias + bn + tid) : 0.f;
    __syncthreads();

    auto load_stage = [&](int s) {
        const int buf = s % 3;
        const int k0 = s * 32;
        char* dA = sAc + buf * 8192;
        char* dB = sBc + buf * 8192;
#pragma unroll
        for (int t = 0; t < 2; ++t) {
            int idx = tid + t * 256;
            int row = idx >> 2, j = idx & 3;
            cp_async16(dA + row * 64 + ((j ^ (row & 3)) << 4),
                       A + (size_t)min(bm + row, M - 1) * K + k0 + j * 8);
        }
#pragma unroll
        for (int t = 0; t < 2; ++t) {
            int idx = tid + t * 256;
            int n = idx >> 2, j = idx & 3;
            cp_async16(dB + n * 64 + ((j ^ (n & 3)) << 4),
                       Bt + (size_t)(bn + n) * K + k0 + j * 8);
        }
    };

    float cf[4][4][4] = {};
    load_stage(0); cp_commit();
    if (NS > 1) { load_stage(1); cp_commit(); }

    for (int s = 0; s < NS; ++s) {
        if (s + 1 < NS) cp_wait1(); else cp_wait0();
        __syncthreads();
        if (s + 2 < NS) { load_stage(s + 2); cp_commit(); }

        const char* fA = sAc + (s % 3) * 8192;
        const char* fB = sBc + (s % 3) * 8192;
#pragma unroll
        for (int g = 0; g < 2; ++g) {
            const int coff = (((g * 2 + (c >> 1)) ^ (r & 3)) << 4) + (c & 1) * 8;
            uint2 ua[4], ub_[4], ubv[4];
#pragma unroll
            for (int ma = 0; ma < 4; ++ma) {
                const int row0 = wm + ma * 16 + r;
                ua[ma]  = *(const uint2*)(fA + row0 * 64 + coff);
                ub_[ma] = *(const uint2*)(fA + (row0 + 8) * 64 + coff);
            }
#pragma unroll
            for (int na = 0; na < 4; ++na)
                ubv[na] = *(const uint2*)(fB + (wnl + na * 8 + r) * 64 + coff);
#pragma unroll
            for (int ma = 0; ma < 4; ++ma)
#pragma unroll
                for (int na = 0; na < 4; ++na)
                    mma16816(cf[ma][na], ua[ma].x, ub_[ma].x, ua[ma].y, ub_[ma].y,
                             ubv[na].x, ubv[na].y);
        }
    }
    __syncthreads();

    float2 bias2[4];
#pragma unroll
    for (int na = 0; na < 4; ++na)
        bias2[na] = *(const float2*)&sBias[wnl + na * 8 + 2 * c];

#pragma unroll
    for (int ma = 0; ma < 4; ++ma) {
        const int row0 = bm + wm + ma * 16 + r;
        const int row1 = row0 + 8;
#pragma unroll
        for (int na = 0; na < 4; ++na) {
            const int nloc = wnl + na * 8 + 2 * c;
            const int pcol = bn + (nloc & ~15) + 4 * c + 2 * ((nloc >> 3) & 1);
            float v0 = cf[ma][na][0] + bias2[na].x;
            float v1 = cf[ma][na][1] + bias2[na].y;
            float v2 = cf[ma][na][2] + bias2[na].x;
            float v3 = cf[ma][na][3] + bias2[na].y;
            if (RELU) {
                v0 = fmaxf(v0, 0.f); v1 = fmaxf(v1, 0.f);
                v2 = fmaxf(v2, 0.f); v3 = fmaxf(v3, 0.f);
            }
            if (row0 < M) {
                __half2 h; h.x = __float2half_rn(v0); h.y = __float2half_rn(v1);
                *(__half2*)(Cmat + (size_t)row0 * N + pcol) = h;
            }
            if (row1 < M) {
                __half2 h; h.x = __float2half_rn(v2); h.y = __float2half_rn(v3);
                *(__half2*)(Cmat + (size_t)row1 * N + pcol) = h;
            }
        }
    }
}

// ============================================================================
// Fused edge kernel: per-CTA 64 edges, everything in smem.
//  P0: edge_f = relu(eattr@We+be)          -> sEf (4 stage-tiles, 16KB)
//  P1: Q = edge_f @ W1c                    -> sQ  (16 stage-tiles, 64KB)
//  P2: A = relu(Pa[src]+Pb[dst]+Q) in place; out = relu(A@W2+b2).W3 + b3
// Stage-tile layout (64 rows x 64B): addr = tile + row*64 + ((j^(row&3))<<4).
// ============================================================================
__global__ __launch_bounds__(256, 2)
void fq_kernel(const float* __restrict__ eattr,
               const float* __restrict__ be, const float* __restrict__ b2,
               const float* __restrict__ W3, const float* __restrict__ b3,
               float* __restrict__ outv, int M)
{
    extern __shared__ char smc[];
    char* sQ  = smc;            // 16 x 4096
    char* sEf = smc + 65536;    // 4 x 4096
    char* sStr = smc + 81920;   // 32768 stream region

    const int tid  = threadIdx.x;
    const int lane = tid & 31;
    const int warp = tid >> 5;
    const int r    = lane >> 2;
    const int c    = lane & 3;
    const int bm   = blockIdx.x * 64;

    // epilogue-to-stage-tiles store (cols kperm'd); nloc even, v0@nloc v1@nloc+1
    auto stsC = [&](char* tiles, int row, int nloc, float v0, float v1) {
        const int pcol = (nloc & ~15) + 4 * c + 2 * ((nloc >> 3) & 1);
        const int stage = pcol >> 5;
        const int byte = (pcol & 31) * 2;
        const int j = byte >> 4;
        __half2 h; h.x = __float2half_rn(v0); h.y = __float2half_rn(v1);
        *(__half2*)(tiles + stage * 4096 + row * 64 + ((j ^ (row & 3)) << 4) + (byte & 15)) = h;
    };

    // ================= Phase 0: edge encoder =================
    {
        char* sA0 = sStr;             // 2 x 4096
        char* sB0 = sStr + 8192;      // 2 x 8192
        float* sBe = (float*)(sStr + 24576);   // 128 f32

        if (tid < 128) sBe[tid] = __ldg(be + tid);
        // B: Wet, 2 stage-tiles of 128 rows x 64B
#pragma unroll
        for (int t = 0; t < 4; ++t) {
            int idx = tid + t * 256;
            int stage = idx >> 9, rem = idx & 511;
            int n = rem >> 2, j = rem & 3;
            cp_async16(sB0 + stage * 8192 + n * 64 + ((j ^ (n & 3)) << 4),
                       g_wet + (size_t)n * 64 + stage * 32 + j * 8);
        }
        cp_commit();
        // A: eattr f32 -> fp16 kperm; thread = (row, 16-group seg)
        {
            const int row = tid >> 2, seg = tid & 3;
            const int e = min(bm + row, M - 1);
            const float* es = eattr + (size_t)e * 64 + seg * 16;
            float ff[16];
#pragma unroll
            for (int q4 = 0; q4 < 4; ++q4) {
                float4 v = __ldg((const float4*)(es + q4 * 4));
                ff[q4 * 4] = v.x; ff[q4 * 4 + 1] = v.y;
                ff[q4 * 4 + 2] = v.z; ff[q4 * 4 + 3] = v.w;
            }
            __half arr[16];
#pragma unroll
            for (int kk = 0; kk < 16; ++kk) {
                int p = (((kk & 7) >> 1) << 2) + (kk & 1) + (((kk >> 3) & 1) << 1);
                arr[p] = __float2half_rn(ff[kk]);
            }
            const int stage = seg >> 1, jb = (seg & 1) * 2;
            char* base = sA0 + stage * 4096 + row * 64;
            *(uint4*)(base + (((jb    ) ^ (row & 3)) << 4)) = *(uint4*)arr;
            *(uint4*)(base + (((jb + 1) ^ (row & 3)) << 4)) = *(uint4*)(arr + 8);
        }
        cp_wait0();
        __syncthreads();

        const int wm0 = (warp >> 2) * 32;
        const int wnl0 = (warp & 3) * 32;
        float cf0[2][4][4] = {};
#pragma unroll
        for (int s0 = 0; s0 < 2; ++s0) {
            const char* fA = sA0 + s0 * 4096;
            const char* fB = sB0 + s0 * 8192;
#pragma unroll
            for (int g = 0; g < 2; ++g) {
                const int coff = (((g * 2 + (c >> 1)) ^ (r & 3)) << 4) + (c & 1) * 8;
                uint2 ua[2], ub_[2], ubv[4];
#pragma unroll
                for (int ma = 0; ma < 2; ++ma) {
                    const int row0 = wm0 + ma * 16 + r;
                    ua[ma]  = *(const uint2*)(fA + row0 * 64 + coff);
                    ub_[ma] = *(const uint2*)(fA + (row0 + 8) * 64 + coff);
                }
#pragma unroll
                for (int na = 0; na < 4; ++na)
                    ubv[na] = *(const uint2*)(fB + (wnl0 + na * 8 + r) * 64 + coff);
#pragma unroll
                for (int ma = 0; ma < 2; ++ma)
#pragma unroll
                    for (int na = 0; na < 4; ++na)
                        mma16816(cf0[ma][na], ua[ma].x, ub_[ma].x, ua[ma].y, ub_[ma].y,
                                 ubv[na].x, ubv[na].y);
            }
        }
        __syncthreads();   // sA0/sB0 dead; sEf writes next
#pragma unroll
        for (int ma = 0; ma < 2; ++ma) {
            const int row0 = wm0 + ma * 16 + r;
#pragma unroll
            for (int na = 0; na < 4; ++na) {
                const int nloc = wnl0 + na * 8 + 2 * c;
                float b0 = sBe[nloc], b1v = sBe[nloc + 1];
                stsC(sEf, row0,     nloc, fmaxf(cf0[ma][na][0] + b0, 0.f),
                                          fmaxf(cf0[ma][na][1] + b1v, 0.f));
                stsC(sEf, row0 + 8, nloc, fmaxf(cf0[ma][na][2] + b0, 0.f),
                                          fmaxf(cf0[ma][na][3] + b1v, 0.f));
            }
        }
        __syncthreads();
    }

    // ================= Phase 1: Q = edge_f @ W1c (2 passes of N=256) ========
    {
        const int wnl = warp * 32;
        auto cpB1 = [&](int np, int s) {
            char* dB = sStr + (s & 1) * 16384;
#pragma unroll
            for (int t = 0; t < 4; ++t) {
                int idx = tid + t * 256;
                int n = idx >> 2, j = idx & 3;
                cp_async16(dB + n * 64 + ((j ^ (n & 3)) << 4),
                           g_w1c + (size_t)(np * 256 + n) * 128 + s * 32 + j * 8);
            }
        };
#pragma unroll
        for (int np = 0; np < 2; ++np) {
            float cf1[4][4][4] = {};
            cpB1(np, 0); cp_commit();
            cpB1(np, 1); cp_commit();
#pragma unroll
            for (int s = 0; s < 4; ++s) {
                if (s + 1 < 4) cp_wait1(); else cp_wait0();
                __syncthreads();
                const char* fA = sEf + s * 4096;
                const char* fB = sStr + (s & 1) * 16384;
#pragma unroll
                for (int g = 0; g < 2; ++g) {
                    const int coff = (((g * 2 + (c >> 1)) ^ (r & 3)) << 4) + (c & 1) * 8;
                    uint2 ua[4], ub_[4], ubv[4];
#pragma unroll
                    for (int ma = 0; ma < 4; ++ma) {
                        const int row0 = ma * 16 + r;
                        ua[ma]  = *(const uint2*)(fA + row0 * 64 + coff);
                        ub_[ma] = *(const uint2*)(fA + (row0 + 8) * 64 + coff);
                    }
#pragma unroll
                    for (int na = 0; na < 4; ++na)
                        ubv[na] = *(const uint2*)(fB + (wnl + na * 8 + r) * 64 + coff);
#pragma unroll
                    for (int ma = 0; ma < 4; ++ma)
#pragma unroll
                        for (int na = 0; na < 4; ++na)
                            mma16816(cf1[ma][na], ua[ma].x, ub_[ma].x, ua[ma].y, ub_[ma].y,
                                     ubv[na].x, ubv[na].y);
                }
                __syncthreads();
                if (s + 2 < 4) { cpB1(np, s + 2); cp_commit(); }
            }
            // write Q pass (no bias/relu)
#pragma unroll
            for (int ma = 0; ma < 4; ++ma) {
                const int row0 = ma * 16 + r;
#pragma unroll
                for (int na = 0; na < 4; ++na) {
                    const int nloc = np * 256 + wnl + na * 8 + 2 * c;
                    stsC(sQ, row0,     nloc, cf1[ma][na][0], cf1[ma][na][1]);
                    stsC(sQ, row0 + 8, nloc, cf1[ma][na][2], cf1[ma][na][3]);
                }
            }
            __syncthreads();
        }
    }

    // ================= Phase 2: W2 + W3 =================
    {
        float* sB2 = (float*)sEf;            // 256 f32
        float* sW3 = (float*)(sEf + 1024);   // 256 f32
        float* psum = (float*)(sEf + 2048);  // 64 x 8 f32
        sB2[tid] = __ldg(b2 + tid);
        sW3[tid] = __ldg(W3 + tid);

        const int row = tid >> 2, j = tid & 3;
        const int e = min(bm + row, M - 1);
        const __half* paP = g_pab + (size_t)g_src[e] * 1024;
        const __half* pbP = g_pab + (size_t)g_dst[e] * 1024 + 512;
        char* qaddrBase = sQ + row * 64 + ((j ^ (row & 3)) << 4);

        uint4 ra, rb;
        auto ldgA = [&](int s) {
            ra = __ldg((const uint4*)(paP + s * 32 + j * 8));
            rb = __ldg((const uint4*)(pbP + s * 32 + j * 8));
        };
        auto finA = [&](int s) {
            uint4 q4 = *(uint4*)(qaddrBase + s * 4096);
            const half2* qh = (const half2*)&q4;
            const half2* ha = (const half2*)&ra;
            const half2* hb = (const half2*)&rb;
            half2 v[4];
            const half2 z = __float2half2_rn(0.f);
#pragma unroll
            for (int i = 0; i < 4; ++i)
                v[i] = __hmax2(__hadd2(__hadd2(qh[i], ha[i]), hb[i]), z);
            *(uint4*)(qaddrBase + s * 4096) = *(uint4*)v;
        };
        auto cpB2 = [&](int s) {
            char* dB = sStr + (s & 1) * 16384;
#pragma unroll
            for (int t = 0; t < 4; ++t) {
                int idx = tid + t * 256;
                int n = idx >> 2, j2 = idx & 3;
                cp_async16(dB + n * 64 + ((j2 ^ (n & 3)) << 4),
                           g_w2t + (size_t)n * 512 + s * 32 + j2 * 8);
            }
        };

        const int wnl = warp * 32;
        float cf[4][4][4] = {};

        ldgA(0);
        cpB2(0); cp_commit();
        cpB2(1); cp_commit();

#pragma unroll 1
        for (int s = 0; s < 16; ++s) {
            finA(s);
            if (s + 1 < 16) ldgA(s + 1);
            if (s + 1 < 16) cp_wait1(); else cp_wait0();
            __syncthreads();
            const char* fA = sQ + s * 4096;
            const char* fB = sStr + (s & 1) * 16384;
#pragma unroll
            for (int g = 0; g < 2; ++g) {
                const int coff = (((g * 2 + (c >> 1)) ^ (r & 3)) << 4) + (c & 1) * 8;
                uint2 ua[4], ub_[4], ubv[4];
#pragma unroll
                for (int ma = 0; ma < 4; ++ma) {
                    const int row0 = ma * 16 + r;
                    ua[ma]  = *(const uint2*)(fA + row0 * 64 + coff);
                    ub_[ma] = *(const uint2*)(fA + (row0 + 8) * 64 + coff);
                }
#pragma unroll
                for (int na = 0; na < 4; ++na)
                    ubv[na] = *(const uint2*)(fB + (wnl + na * 8 + r) * 64 + coff);
#pragma unroll
                for (int ma = 0; ma < 4; ++ma)
#pragma unroll
                    for (int na = 0; na < 4; ++na)
                        mma16816(cf[ma][na], ua[ma].x, ub_[ma].x, ua[ma].y, ub_[ma].y,
                                 ubv[na].x, ubv[na].y);
            }
            __syncthreads();
            if (s + 2 < 16) { cpB2(s + 2); cp_commit(); }
        }

        float2 bias2[4], w3v[4];
#pragma unroll
        for (int na = 0; na < 4; ++na) {
            bias2[na] = *(const float2*)&sB2[wnl + na * 8 + 2 * c];
            w3v[na]   = *(const float2*)&sW3[wnl + na * 8 + 2 * c];
        }
#pragma unroll
        for (int ma = 0; ma < 4; ++ma) {
            float p0 = 0.f, p1 = 0.f;
#pragma unroll
            for (int na = 0; na < 4; ++na) {
                p0 += fmaxf(cf[ma][na][0] + bias2[na].x, 0.f) * w3v[na].x
                    + fmaxf(cf[ma][na][1] + bias2[na].y, 0.f) * w3v[na].y;
                p1 += fmaxf(cf[ma][na][2] + bias2[na].x, 0.f) * w3v[na].x
                    + fmaxf(cf[ma][na][3] + bias2[na].y, 0.f) * w3v[na].y;
            }
            p0 += __shfl_xor_sync(0xffffffffu, p0, 1);
            p0 += __shfl_xor_sync(0xffffffffu, p0, 2);
            p1 += __shfl_xor_sync(0xffffffffu, p1, 1);
            p1 += __shfl_xor_sync(0xffffffffu, p1, 2);
            if (c == 0) {
                const int rl = ma * 16 + r;
                psum[rl * 8 + warp] = p0;
                psum[(rl + 8) * 8 + warp] = p1;
            }
        }
        __syncthreads();
        if (tid < 64) {
            const int gm = bm + tid;
            if (gm < M) {
                float s = 0.f;
#pragma unroll
                for (int w = 0; w < 8; ++w) s += psum[tid * 8 + w];
                outv[gm] = s + __ldg(b3);
            }
        }
    }
}

// ============================================================================
extern "C" void kernel_launch(void* const* d_in, const int* in_sizes, int n_in,
                              void* d_out, int out_size)
{
    const float* x     = (const float*)d_in[0];
    const void*  eidx  = d_in[1];
    const float* eattr = (const float*)d_in[2];
    const float* Wn    = (const float*)d_in[3];
    const float* bnode = (const float*)d_in[4];
    const float* We    = (const float*)d_in[5];
    const float* be    = (const float*)d_in[6];
    const float* W1    = (const float*)d_in[7];
    const float* b1    = (const float*)d_in[8];
    const float* W2    = (const float*)d_in[9];
    const float* b2    = (const float*)d_in[10];
    const float* W3    = (const float*)d_in[11];
    const float* b3    = (const float*)d_in[12];
    float* out = (float*)d_out;

    __half *p_node, *p_pab, *p_xt, *p_wnt, *p_wet, *p_w1ab, *p_w1c, *p_w2t;
    float* p_b1024;
    cudaGetSymbolAddress((void**)&p_node, g_node_f);
    cudaGetSymbolAddress((void**)&p_pab, g_pab);
    cudaGetSymbolAddress((void**)&p_xt, g_xt);
    cudaGetSymbolAddress((void**)&p_wnt, g_wnt);
    cudaGetSymbolAddress((void**)&p_wet, g_wet);
    cudaGetSymbolAddress((void**)&p_w1ab, g_w1ab);
    cudaGetSymbolAddress((void**)&p_w1c, g_w1c);
    cudaGetSymbolAddress((void**)&p_w2t, g_w2t);
    cudaGetSymbolAddress((void**)&p_b1024, g_bias1024);

    detect_idx_kernel<<<1, 32>>>(eidx);
    conv_idx_kernel<<<(kEdges + 255) / 256, 256>>>(eidx);

    perm_round_kernel<<<(kNodes * 128 + 255) / 256, 256>>>(x, p_xt, kNodes * 128, 128);
    trans_round_kernel<<<(128 * 128 + 255) / 256, 256>>>(Wn, p_wnt, 128, 128);
    trans_round_kernel<<<(64 * 128 + 255) / 256, 256>>>(We, p_wet, 64, 128);
    trans_round_kernel<<<(512 * 256 + 255) / 256, 256>>>(W2, p_w2t, 512, 256);
    trans_w1ab_kernel<<<(1024 * 128 + 255) / 256, 256>>>(W1, p_w1ab);
    trans_w1c_kernel<<<(512 * 128 + 255) / 256, 256>>>(W1, p_w1c);
    bias1024_kernel<<<4, 256>>>(b1, p_b1024);

    // node encoder [50000,128]
    cudaFuncSetAttribute(mm_kernel<128, 128, true>,
                         cudaFuncAttributeMaxDynamicSharedMemorySize, MM_SMEM);
    mm_kernel<128, 128, true><<<dim3(1, (kNodes + 127) / 128), 256, MM_SMEM>>>(
        p_xt, p_wnt, bnode, p_node, kNodes);

    // Pab = node_f @ [W1a|W1b] + [b1|0]   [50000,1024]
    cudaFuncSetAttribute(mm_kernel<128, 1024, false>,
                         cudaFuncAttributeMaxDynamicSharedMemorySize, MM_SMEM);
    mm_kernel<128, 1024, false><<<dim3(8, (kNodes + 127) / 128), 256, MM_SMEM>>>(
        p_node, p_w1ab, p_b1024, p_pab, kNodes);

    // fused edge pipeline
    cudaFuncSetAttribute(fq_kernel,
                         cudaFuncAttributeMaxDynamicSharedMemorySize, FQ_SMEM);
    fq_kernel<<<(kEdges + 63) / 64, 256, FQ_SMEM>>>(eattr, be, b2, W3, b3, out, kEdges);
}